// round 2
// baseline (speedup 1.0000x reference)
#include <cuda_runtime.h>
#include <math_constants.h>

#define BB 2
#define NN 2048
#define FF 512
#define DD 512
#define EE 1536   // 3*DD
#define WW 128

// scratch for qkv: [B*N][3D] row-major
__device__ float g_qkv[BB * NN * EE];

// ---------------------------------------------------------------------------
// Kernel 1: QKV GEMM.  C[m][e] = sum_f X[m][f] * Wl[e][f]
// M = 4096, E = 1536, K = 512.  BM=BN=128, BK=16, 256 threads, 8x8 microtile.
// ---------------------------------------------------------------------------
__global__ __launch_bounds__(256, 2)
void qkv_gemm_kernel(const float* __restrict__ X, const float* __restrict__ Wl) {
    __shared__ float sA[16][132];
    __shared__ float sB[16][132];

    const int tid = threadIdx.x;
    const int bm = blockIdx.y * 128;
    const int bn = blockIdx.x * 128;
    const int tx = tid & 15;    // col group
    const int ty = tid >> 4;    // row group

    float acc[8][8];
#pragma unroll
    for (int i = 0; i < 8; ++i)
#pragma unroll
        for (int j = 0; j < 8; ++j) acc[i][j] = 0.f;

    for (int k0 = 0; k0 < FF; k0 += 16) {
        // load tiles (transposed into smem): 128 rows x 16 cols each
#pragma unroll
        for (int it = 0; it < 2; ++it) {
            int idx = tid + it * 256;        // 0..511
            int row = idx >> 2;              // 0..127
            int c4  = (idx & 3) << 2;        // 0,4,8,12
            float4 a = *(const float4*)&X[(bm + row) * FF + k0 + c4];
            sA[c4 + 0][row] = a.x; sA[c4 + 1][row] = a.y;
            sA[c4 + 2][row] = a.z; sA[c4 + 3][row] = a.w;
            float4 b = *(const float4*)&Wl[(bn + row) * FF + k0 + c4];
            sB[c4 + 0][row] = b.x; sB[c4 + 1][row] = b.y;
            sB[c4 + 2][row] = b.z; sB[c4 + 3][row] = b.w;
        }
        __syncthreads();

#pragma unroll
        for (int k = 0; k < 16; ++k) {
            float af[8], bf[8];
            *(float4*)&af[0] = *(const float4*)&sA[k][ty * 8];
            *(float4*)&af[4] = *(const float4*)&sA[k][ty * 8 + 4];
            *(float4*)&bf[0] = *(const float4*)&sB[k][tx * 8];
            *(float4*)&bf[4] = *(const float4*)&sB[k][tx * 8 + 4];
#pragma unroll
            for (int i = 0; i < 8; ++i)
#pragma unroll
                for (int j = 0; j < 8; ++j)
                    acc[i][j] = fmaf(af[i], bf[j], acc[i][j]);
        }
        __syncthreads();
    }

#pragma unroll
    for (int i = 0; i < 8; ++i) {
        int row = bm + ty * 8 + i;
        float4 v0 = make_float4(acc[i][0], acc[i][1], acc[i][2], acc[i][3]);
        float4 v1 = make_float4(acc[i][4], acc[i][5], acc[i][6], acc[i][7]);
        *(float4*)&g_qkv[row * EE + bn + tx * 8]     = v0;
        *(float4*)&g_qkv[row * EE + bn + tx * 8 + 4] = v1;
    }
}

// ---------------------------------------------------------------------------
// Kernel 2: sliding-window attention.
// One block per 32 queries. Window union = 159 key rows (+1 zero pad = 160).
// Phase A: S[i][r] = q[q0+i] . k[q0-127+r]  (dense 32x160x512 GEMM in smem)
// Softmax over band w = r - i in [0,128), matching reference's zero-padding
// (OOB keys give logit 0 and participate in the softmax; v is zero there).
// Phase B: out[i][d] = sum_r attn[i][r] * v[q0-127+r][d], v streamed from L1.
// ---------------------------------------------------------------------------
__global__ __launch_bounds__(256, 1)
void attn_kernel(float* __restrict__ out) {
    __shared__ float sS[32 * 161];    // scores, stride 161
    __shared__ float sAtt[32 * 160];  // attn weights (zeros outside band)
    __shared__ float sK[160 * 33];    // k chunk [160 rows][32 f], stride 33
    __shared__ float sQ[32 * 33];     // q chunk

    const int tid = threadIdx.x;
    const int b   = blockIdx.y;
    const int q0  = blockIdx.x * 32;
    const float* base = g_qkv + (size_t)b * NN * EE;

    // ---- Phase A: S = Q . K^T over window union ----
    const int ig = tid >> 5;   // 0..7 : i = 4*ig + a
    const int rg = tid & 31;   // r = 5*rg + j, j = 0..4  (covers 0..159)

    float acc[4][5];
#pragma unroll
    for (int a = 0; a < 4; ++a)
#pragma unroll
        for (int j = 0; j < 5; ++j) acc[a][j] = 0.f;

    for (int f0 = 0; f0 < FF; f0 += 32) {
        // sQ: 32 rows x 32 f  (256 float4 = 1 per thread)
        {
            int row = tid >> 3;
            int c   = (tid & 7) << 2;
            float4 v = *(const float4*)&base[(q0 + row) * EE + f0 + c];
            sQ[row * 33 + c + 0] = v.x; sQ[row * 33 + c + 1] = v.y;
            sQ[row * 33 + c + 2] = v.z; sQ[row * 33 + c + 3] = v.w;
        }
        // sK: 160 rows x 32 f  (1280 float4 = 5 per thread), zero OOB rows
#pragma unroll
        for (int it = 0; it < 5; ++it) {
            int idx = tid + it * 256;    // 0..1279
            int row = idx >> 3;          // 0..159
            int c   = (idx & 7) << 2;
            int n   = q0 - 127 + row;
            float4 v = make_float4(0.f, 0.f, 0.f, 0.f);
            if (n >= 0 && n < NN)
                v = *(const float4*)&base[n * EE + DD + f0 + c];
            sK[row * 33 + c + 0] = v.x; sK[row * 33 + c + 1] = v.y;
            sK[row * 33 + c + 2] = v.z; sK[row * 33 + c + 3] = v.w;
        }
        __syncthreads();

#pragma unroll
        for (int f = 0; f < 32; ++f) {
            float qv[4], kv[5];
#pragma unroll
            for (int a = 0; a < 4; ++a) qv[a] = sQ[(4 * ig + a) * 33 + f];
#pragma unroll
            for (int j = 0; j < 5; ++j) kv[j] = sK[(5 * rg + j) * 33 + f];
#pragma unroll
            for (int a = 0; a < 4; ++a)
#pragma unroll
                for (int j = 0; j < 5; ++j)
                    acc[a][j] = fmaf(qv[a], kv[j], acc[a][j]);
        }
        __syncthreads();
    }

#pragma unroll
    for (int a = 0; a < 4; ++a)
#pragma unroll
        for (int j = 0; j < 5; ++j)
            sS[(4 * ig + a) * 161 + 5 * rg + j] = acc[a][j];
    __syncthreads();

    // ---- Softmax per row over the 128-wide band ----
    {
        const int wid  = tid >> 5;
        const int lane = tid & 31;
#pragma unroll
        for (int ii = 0; ii < 4; ++ii) {
            int i = wid * 4 + ii;
            float vals[4];
            float m = -CUDART_INF_F;
#pragma unroll
            for (int t = 0; t < 4; ++t) {
                vals[t] = sS[i * 161 + i + lane + 32 * t];  // w = lane+32t
                m = fmaxf(m, vals[t]);
            }
#pragma unroll
            for (int o = 16; o > 0; o >>= 1)
                m = fmaxf(m, __shfl_xor_sync(0xffffffffu, m, o));
            float s = 0.f;
#pragma unroll
            for (int t = 0; t < 4; ++t) s += __expf(vals[t] - m);
#pragma unroll
            for (int o = 16; o > 0; o >>= 1)
                s += __shfl_xor_sync(0xffffffffu, s, o);
            float inv = 1.f / s;
            // write attn, zeroing outside the band (r in [0,160))
#pragma unroll
            for (int t = 0; t < 5; ++t) {
                int r = lane + 32 * t;
                int w = r - i;
                float val = 0.f;
                if (w >= 0 && w < WW)
                    val = __expf(sS[i * 161 + r] - m) * inv;
                sAtt[i * 160 + r] = val;
            }
        }
    }
    __syncthreads();

    // ---- Phase B: out = attn . V  (v streamed from global/L1) ----
    {
        const int dg = tid & 31;  // d = 4*dg + 128*j + c
        float o[4][16];
#pragma unroll
        for (int a = 0; a < 4; ++a)
#pragma unroll
            for (int j = 0; j < 16; ++j) o[a][j] = 0.f;

        for (int r = 0; r < 159; ++r) {
            int n = q0 - 127 + r;
            if (n < 0) continue;   // v padded zero -> no contribution
            float av[4];
#pragma unroll
            for (int a = 0; a < 4; ++a) av[a] = sAtt[(4 * ig + a) * 160 + r];
            const float* vrow = &base[n * EE + 2 * DD];
#pragma unroll
            for (int j = 0; j < 4; ++j) {
                float4 vv = *(const float4*)&vrow[4 * dg + 128 * j];
#pragma unroll
                for (int a = 0; a < 4; ++a) {
                    o[a][4 * j + 0] = fmaf(av[a], vv.x, o[a][4 * j + 0]);
                    o[a][4 * j + 1] = fmaf(av[a], vv.y, o[a][4 * j + 1]);
                    o[a][4 * j + 2] = fmaf(av[a], vv.z, o[a][4 * j + 2]);
                    o[a][4 * j + 3] = fmaf(av[a], vv.w, o[a][4 * j + 3]);
                }
            }
        }

#pragma unroll
        for (int a = 0; a < 4; ++a) {
            int row = q0 + 4 * ig + a;
            float* orow = out + ((size_t)b * NN + row) * DD;
#pragma unroll
            for (int j = 0; j < 4; ++j) {
                float4 vv = make_float4(o[a][4 * j + 0], o[a][4 * j + 1],
                                        o[a][4 * j + 2], o[a][4 * j + 3]);
                *(float4*)&orow[4 * dg + 128 * j] = vv;
            }
        }
    }
}

extern "C" void kernel_launch(void* const* d_in, const int* in_sizes, int n_in,
                              void* d_out, int out_size) {
    const float* x  = (const float*)d_in[0];
    const float* wl = (const float*)d_in[1];
    float* out = (float*)d_out;

    dim3 g1(EE / 128, (BB * NN) / 128);   // 12 x 32
    qkv_gemm_kernel<<<g1, 256>>>(x, wl);

    dim3 g2(NN / 32, BB);                 // 64 x 2
    attn_kernel<<<g2, 256>>>(out);
}

// round 3
// speedup vs baseline: 1.0772x; 1.0772x over previous
#include <cuda_runtime.h>
#include <math_constants.h>

#define BB 2
#define NN 2048
#define FF 512
#define DD 512
#define EE 1536   // 3*DD
#define WW 128

// scratch for qkv: [B*N][3D] row-major
__device__ float g_qkv[BB * NN * EE];

// ---------------------------------------------------------------------------
// Kernel 1: QKV GEMM.  C[m][e] = sum_f X[m][f] * Wl[e][f]
// M = 4096, E = 1536, K = 512.  BM=BN=128, BK=16, 256 threads, 8x8 microtile.
// Register-prefetch double buffering on the k-loop.
// ---------------------------------------------------------------------------
__global__ __launch_bounds__(256, 2)
void qkv_gemm_kernel(const float* __restrict__ X, const float* __restrict__ Wl) {
    __shared__ float sA[16][132];
    __shared__ float sB[16][132];

    const int tid = threadIdx.x;
    const int bm = blockIdx.y * 128;
    const int bn = blockIdx.x * 128;
    const int tx = tid & 15;    // col group
    const int ty = tid >> 4;    // row group
    const int lrow = tid >> 2;          // 0..63
    const int lc   = (tid & 3) << 2;    // 0,4,8,12

    float acc[8][8];
#pragma unroll
    for (int i = 0; i < 8; ++i)
#pragma unroll
        for (int j = 0; j < 8; ++j) acc[i][j] = 0.f;

    // prologue: load k-tile 0 into smem
    {
        float4 a0 = *(const float4*)&X[(bm + lrow) * FF + lc];
        float4 a1 = *(const float4*)&X[(bm + lrow + 64) * FF + lc];
        float4 b0 = *(const float4*)&Wl[(bn + lrow) * FF + lc];
        float4 b1 = *(const float4*)&Wl[(bn + lrow + 64) * FF + lc];
        sA[lc + 0][lrow] = a0.x; sA[lc + 1][lrow] = a0.y;
        sA[lc + 2][lrow] = a0.z; sA[lc + 3][lrow] = a0.w;
        sA[lc + 0][lrow + 64] = a1.x; sA[lc + 1][lrow + 64] = a1.y;
        sA[lc + 2][lrow + 64] = a1.z; sA[lc + 3][lrow + 64] = a1.w;
        sB[lc + 0][lrow] = b0.x; sB[lc + 1][lrow] = b0.y;
        sB[lc + 2][lrow] = b0.z; sB[lc + 3][lrow] = b0.w;
        sB[lc + 0][lrow + 64] = b1.x; sB[lc + 1][lrow + 64] = b1.y;
        sB[lc + 2][lrow + 64] = b1.z; sB[lc + 3][lrow + 64] = b1.w;
    }
    __syncthreads();

    for (int k0 = 0; k0 < FF; k0 += 16) {
        float4 na0, na1, nb0, nb1;
        const bool has_next = (k0 + 16) < FF;
        if (has_next) {
            int kn = k0 + 16;
            na0 = *(const float4*)&X[(bm + lrow) * FF + kn + lc];
            na1 = *(const float4*)&X[(bm + lrow + 64) * FF + kn + lc];
            nb0 = *(const float4*)&Wl[(bn + lrow) * FF + kn + lc];
            nb1 = *(const float4*)&Wl[(bn + lrow + 64) * FF + kn + lc];
        }

#pragma unroll
        for (int k = 0; k < 16; ++k) {
            float af[8], bf[8];
            *(float4*)&af[0] = *(const float4*)&sA[k][ty * 8];
            *(float4*)&af[4] = *(const float4*)&sA[k][ty * 8 + 4];
            *(float4*)&bf[0] = *(const float4*)&sB[k][tx * 8];
            *(float4*)&bf[4] = *(const float4*)&sB[k][tx * 8 + 4];
#pragma unroll
            for (int i = 0; i < 8; ++i)
#pragma unroll
                for (int j = 0; j < 8; ++j)
                    acc[i][j] = fmaf(af[i], bf[j], acc[i][j]);
        }
        __syncthreads();

        if (has_next) {
            sA[lc + 0][lrow] = na0.x; sA[lc + 1][lrow] = na0.y;
            sA[lc + 2][lrow] = na0.z; sA[lc + 3][lrow] = na0.w;
            sA[lc + 0][lrow + 64] = na1.x; sA[lc + 1][lrow + 64] = na1.y;
            sA[lc + 2][lrow + 64] = na1.z; sA[lc + 3][lrow + 64] = na1.w;
            sB[lc + 0][lrow] = nb0.x; sB[lc + 1][lrow] = nb0.y;
            sB[lc + 2][lrow] = nb0.z; sB[lc + 3][lrow] = nb0.w;
            sB[lc + 0][lrow + 64] = nb1.x; sB[lc + 1][lrow + 64] = nb1.y;
            sB[lc + 2][lrow + 64] = nb1.z; sB[lc + 3][lrow + 64] = nb1.w;
            __syncthreads();
        }
    }

#pragma unroll
    for (int i = 0; i < 8; ++i) {
        int row = bm + ty * 8 + i;
        float4 v0 = make_float4(acc[i][0], acc[i][1], acc[i][2], acc[i][3]);
        float4 v1 = make_float4(acc[i][4], acc[i][5], acc[i][6], acc[i][7]);
        *(float4*)&g_qkv[row * EE + bn + tx * 8]     = v0;
        *(float4*)&g_qkv[row * EE + bn + tx * 8 + 4] = v1;
    }
}

// ---------------------------------------------------------------------------
// Kernel 2: sliding-window attention. 512 threads, 32-query tiles, grid 64x2.
//
// Phase A: S band = Q . K^T.  q via LDS.128 broadcast (warp-uniform ig),
//   k rows r = lane64 + 64j (j=0..2), sK zero-padded to 192 rows so the
//   inner loop is guard-free; only the band w = r - i in [0,128) is stored.
// Softmax per row (16 warps x 2 rows), writes transposed attn sAttT[r][i]
//   with zeros outside the band (matches reference zero-padded softmax).
// Phase B: out = attn . V with 8-row microtile: ig2 = tid>>7 (4 groups),
//   each thread owns one float4 of d; attn read as 2 broadcast LDS.128.
// ---------------------------------------------------------------------------
#define SQ_STRIDE 36
#define SK_STRIDE 197
#define SAT_STRIDE 36

__global__ __launch_bounds__(512, 1)
void attn_kernel(float* __restrict__ out) {
    __shared__ float sSb[32 * 129];   // band scores: [i][w]
    __shared__ float sU[32 * SQ_STRIDE + 32 * SK_STRIDE];  // Phase A: sQ+sK; Phase B: sAttT

    float* const sQ = sU;                              // [32 f][36]
    float* const sK = sU + 32 * SQ_STRIDE;             // [32 f][197] (rows 0..191 used)
    float* const sAttT = sU;                           // [160 r][36]

    const int tid = threadIdx.x;
    const int b   = blockIdx.y;
    const int q0  = blockIdx.x * 32;
    const float* base = g_qkv + (size_t)b * NN * EE;

    const int ig     = tid >> 6;     // 0..7 : i = 4*ig + a
    const int lane64 = tid & 63;     // r = lane64 + 64*j

    // zero sK pad rows 160..191 (once; re-used every f-chunk)
    for (int idx = tid; idx < 32 * 32; idx += 512) {
        int f = idx >> 5;
        int r = 160 + (idx & 31);
        sK[f * SK_STRIDE + r] = 0.f;
    }

    float acc[4][3];
#pragma unroll
    for (int a = 0; a < 4; ++a)
#pragma unroll
        for (int j = 0; j < 3; ++j) acc[a][j] = 0.f;

    for (int f0 = 0; f0 < FF; f0 += 32) {
        // sQ: 32 rows x 32 f (256 float4, first 256 threads)
        if (tid < 256) {
            int row = tid >> 3;
            int c   = (tid & 7) << 2;
            float4 v = *(const float4*)&base[(q0 + row) * EE + f0 + c];
            sQ[(c + 0) * SQ_STRIDE + row] = v.x;
            sQ[(c + 1) * SQ_STRIDE + row] = v.y;
            sQ[(c + 2) * SQ_STRIDE + row] = v.z;
            sQ[(c + 3) * SQ_STRIDE + row] = v.w;
        }
        // sK: 160 rows x 32 f (1280 float4), zero OOB rows
#pragma unroll
        for (int it = 0; it < 3; ++it) {
            int idx = tid + it * 512;
            if (idx < 1280) {
                int row = idx >> 3;          // 0..159
                int c   = (idx & 7) << 2;
                int n   = q0 - 127 + row;
                float4 v = make_float4(0.f, 0.f, 0.f, 0.f);
                if (n >= 0 && n < NN)
                    v = *(const float4*)&base[n * EE + DD + f0 + c];
                sK[(c + 0) * SK_STRIDE + row] = v.x;
                sK[(c + 1) * SK_STRIDE + row] = v.y;
                sK[(c + 2) * SK_STRIDE + row] = v.z;
                sK[(c + 3) * SK_STRIDE + row] = v.w;
            }
        }
        __syncthreads();

#pragma unroll 4
        for (int f = 0; f < 32; ++f) {
            float4 qv = *(const float4*)&sQ[f * SQ_STRIDE + 4 * ig];  // broadcast
            float qa[4] = {qv.x, qv.y, qv.z, qv.w};
            float kv[3];
            kv[0] = sK[f * SK_STRIDE + lane64];
            kv[1] = sK[f * SK_STRIDE + lane64 + 64];
            kv[2] = sK[f * SK_STRIDE + lane64 + 128];
#pragma unroll
            for (int a = 0; a < 4; ++a)
#pragma unroll
                for (int j = 0; j < 3; ++j)
                    acc[a][j] = fmaf(qa[a], kv[j], acc[a][j]);
        }
        __syncthreads();
    }

    // store band scores
#pragma unroll
    for (int a = 0; a < 4; ++a) {
        int i = 4 * ig + a;
#pragma unroll
        for (int j = 0; j < 3; ++j) {
            int r = lane64 + 64 * j;
            int w = r - i;
            if (w >= 0 && w < WW) sSb[i * 129 + w] = acc[a][j];
        }
    }
    __syncthreads();

    // ---- Softmax: 16 warps x 2 rows ----
    {
        const int wid  = tid >> 5;
        const int lane = tid & 31;
#pragma unroll
        for (int ii = 0; ii < 2; ++ii) {
            int i = 2 * wid + ii;
            float vals[4];
            float m = -CUDART_INF_F;
#pragma unroll
            for (int t = 0; t < 4; ++t) {
                vals[t] = sSb[i * 129 + lane + 32 * t];
                m = fmaxf(m, vals[t]);
            }
#pragma unroll
            for (int o = 16; o > 0; o >>= 1)
                m = fmaxf(m, __shfl_xor_sync(0xffffffffu, m, o));
            float s = 0.f;
#pragma unroll
            for (int t = 0; t < 4; ++t) s += __expf(vals[t] - m);
#pragma unroll
            for (int o = 16; o > 0; o >>= 1)
                s += __shfl_xor_sync(0xffffffffu, s, o);
            float inv = 1.f / s;
            // stash per-row (m, inv) in registers for the write pass below
            // write transposed attn (zeros outside band)
#pragma unroll
            for (int t = 0; t < 5; ++t) {
                int r = lane + 32 * t;
                int w = r - i;
                float val = 0.f;
                if (w >= 0 && w < WW)
                    val = __expf(sSb[i * 129 + w] - m) * inv;
                // NOTE: sAttT aliases sQ/sK but sSb is separate, and the
                // band values were read above/here before overwrite of sU.
                sAttT[r * SAT_STRIDE + i] = val;
            }
        }
    }
    __syncthreads();

    // ---- Phase B: out = attn . V ----
    {
        const int ig2     = tid >> 7;    // 0..3 : i = 8*ig2 + a
        const int lane128 = tid & 127;   // d = 4*lane128
        const int d0 = 4 * lane128;
        const float* vbase = base + 2 * DD + d0;

        float4 o4[8];
#pragma unroll
        for (int a = 0; a < 8; ++a) o4[a] = make_float4(0.f, 0.f, 0.f, 0.f);

        const int rstart = (q0 < 127) ? (127 - q0) : 0;
#pragma unroll 2
        for (int r = rstart; r < 159; ++r) {
            int n = q0 - 127 + r;
            float4 av0 = *(const float4*)&sAttT[r * SAT_STRIDE + 8 * ig2];      // bcast
            float4 av1 = *(const float4*)&sAttT[r * SAT_STRIDE + 8 * ig2 + 4];  // bcast
            float4 vv = *(const float4*)&vbase[n * EE];
            float av[8] = {av0.x, av0.y, av0.z, av0.w, av1.x, av1.y, av1.z, av1.w};
#pragma unroll
            for (int a = 0; a < 8; ++a) {
                o4[a].x = fmaf(av[a], vv.x, o4[a].x);
                o4[a].y = fmaf(av[a], vv.y, o4[a].y);
                o4[a].z = fmaf(av[a], vv.z, o4[a].z);
                o4[a].w = fmaf(av[a], vv.w, o4[a].w);
            }
        }

#pragma unroll
        for (int a = 0; a < 8; ++a) {
            int row = q0 + 8 * ig2 + a;
            *(float4*)&out[((size_t)b * NN + row) * DD + d0] = o4[a];
        }
    }
}

extern "C" void kernel_launch(void* const* d_in, const int* in_sizes, int n_in,
                              void* d_out, int out_size) {
    const float* x  = (const float*)d_in[0];
    const float* wl = (const float*)d_in[1];
    float* out = (float*)d_out;

    dim3 g1(EE / 128, (BB * NN) / 128);   // 12 x 32
    qkv_gemm_kernel<<<g1, 256>>>(x, wl);

    dim3 g2(NN / 32, BB);                 // 64 x 2
    attn_kernel<<<g2, 512>>>(out);
}

// round 7
// speedup vs baseline: 1.3876x; 1.2881x over previous
#include <cuda_runtime.h>
#include <cuda_bf16.h>
#include <math_constants.h>
#include <cstdint>

#define BB 2
#define NN 2048
#define FF 512
#define DD 512
#define EE 1536   // 3*DD
#define WW 128

// scratch buffers
__device__ float g_qkv[BB * NN * EE];
__device__ __nv_bfloat16 g_xhi[BB * NN * FF];
__device__ __nv_bfloat16 g_xlo[BB * NN * FF];
__device__ __nv_bfloat16 g_whi[EE * FF];
__device__ __nv_bfloat16 g_wlo[EE * FF];

__device__ __forceinline__ uint32_t smem_u32(const void* p) {
    uint32_t a;
    asm("{ .reg .u64 t; cvta.to.shared.u64 t, %1; cvt.u32.u64 %0, t; }"
        : "=r"(a) : "l"(p));
    return a;
}

// ---------------------------------------------------------------------------
// Conversion: fp32 -> (bf16 hi, bf16 lo) split.  Two variants referencing
// the device globals directly (no symbol-address queries on the host).
// ---------------------------------------------------------------------------
__device__ __forceinline__ void split4(const float* __restrict__ src, int i,
                                       __nv_bfloat16* __restrict__ hi,
                                       __nv_bfloat16* __restrict__ lo) {
    float4 v = ((const float4*)src)[i];
    __nv_bfloat16 h0 = __float2bfloat16_rn(v.x);
    __nv_bfloat16 h1 = __float2bfloat16_rn(v.y);
    __nv_bfloat16 h2 = __float2bfloat16_rn(v.z);
    __nv_bfloat16 h3 = __float2bfloat16_rn(v.w);
    __nv_bfloat16 l0 = __float2bfloat16_rn(v.x - __bfloat162float(h0));
    __nv_bfloat16 l1 = __float2bfloat16_rn(v.y - __bfloat162float(h1));
    __nv_bfloat16 l2 = __float2bfloat16_rn(v.z - __bfloat162float(h2));
    __nv_bfloat16 l3 = __float2bfloat16_rn(v.w - __bfloat162float(h3));
    __nv_bfloat162* hp = (__nv_bfloat162*)hi;
    __nv_bfloat162* lp = (__nv_bfloat162*)lo;
    hp[2 * i]     = __nv_bfloat162{h0, h1};
    hp[2 * i + 1] = __nv_bfloat162{h2, h3};
    lp[2 * i]     = __nv_bfloat162{l0, l1};
    lp[2 * i + 1] = __nv_bfloat162{l2, l3};
}

__global__ void conv_x_kernel(const float* __restrict__ src) {
    int i = blockIdx.x * blockDim.x + threadIdx.x;
    if (i < BB * NN * FF / 4) split4(src, i, g_xhi, g_xlo);
}
__global__ void conv_w_kernel(const float* __restrict__ src) {
    int i = blockIdx.x * blockDim.x + threadIdx.x;
    if (i < EE * FF / 4) split4(src, i, g_whi, g_wlo);
}

// ---------------------------------------------------------------------------
// Kernel 1: QKV GEMM via mma.sync bf16 (split-bf16, 3 accumulation passes).
// C[m][e] = sum_f X[m][f] * W[e][f];  W rows are B^T for .row.col directly.
// CTA tile 128x128, BK=32, 8 warps (4 M x 2 N), warp tile 32x64.
// cp.async double-buffered smem, fp32 accum across 48 K-tiles.
// ---------------------------------------------------------------------------
#define BK 32
#define SROW 40   // bf16 elements per smem row (80B): ldmatrix conflict-free

__global__ __launch_bounds__(256, 2)
void qkv_mma_kernel() {
    __shared__ __nv_bfloat16 sA[2][128 * SROW];
    __shared__ __nv_bfloat16 sB[2][128 * SROW];

    const int tid = threadIdx.x;
    const int lane = tid & 31;
    const int wid = tid >> 5;
    const int wr = wid & 3;     // warp M position (32 rows each)
    const int wc = wid >> 2;    // warp N position (64 cols each)
    const int bn = blockIdx.x * 128;
    const int bm = blockIdx.y * 128;

    // cp.async per-thread: 2 chunks of 16B per tile per operand
    const int c0 = tid * 2;            // chunk ids c0, c0+1 (0..511)
    const int ldr0 = c0 >> 2;          // row of chunk0
    const int ldc0 = (c0 & 3) * 8;     // bf16 col of chunk0

    float acc[2][8][4];
#pragma unroll
    for (int mi = 0; mi < 2; ++mi)
#pragma unroll
        for (int ni = 0; ni < 8; ++ni)
#pragma unroll
            for (int q = 0; q < 4; ++q) acc[mi][ni][q] = 0.f;

    const __nv_bfloat16* APs[3] = {g_xhi, g_xhi, g_xlo};
    const __nv_bfloat16* BPs[3] = {g_whi, g_wlo, g_whi};

    const int NT = 48;   // 3 passes x 16 k-tiles

    // smem byte addresses for this thread's cp.async destinations
    const uint32_t sA0 = smem_u32(sA[0]);
    const uint32_t sB0 = smem_u32(sB[0]);
    const uint32_t dstAoff0 = (uint32_t)(ldr0 * SROW + ldc0) * 2;
    const uint32_t dstAoff1 = (uint32_t)((ldr0)*SROW + ldc0) * 2 + ((c0 + 1) - c0) * 0; // placeholder
    const uint32_t bufStride = 128 * SROW * 2;   // bytes per buffer

    auto issue_loads = [&](int t, int buf) {
        int pass = t >> 4;
        int k0 = (t & 15) * BK;
        const __nv_bfloat16* A = APs[pass] + (size_t)bm * FF + k0;
        const __nv_bfloat16* B = BPs[pass] + (size_t)bn * FF + k0;
#pragma unroll
        for (int j = 0; j < 2; ++j) {
            int c = c0 + j;
            int row = c >> 2;
            int col = (c & 3) * 8;
            uint32_t da = sA0 + buf * bufStride + (uint32_t)(row * SROW + col) * 2;
            uint32_t db = sB0 + buf * bufStride + (uint32_t)(row * SROW + col) * 2;
            const void* ga = A + row * FF + col;
            const void* gb = B + row * FF + col;
            asm volatile("cp.async.cg.shared.global [%0], [%1], 16;"
                         :: "r"(da), "l"(ga) : "memory");
            asm volatile("cp.async.cg.shared.global [%0], [%1], 16;"
                         :: "r"(db), "l"(gb) : "memory");
        }
        asm volatile("cp.async.commit_group;" ::: "memory");
    };

    issue_loads(0, 0);

    // per-warp ldmatrix base addresses
    const int a_row = wr * 32 + (lane & 15);         // + mi*16
    const int a_kc  = (lane >> 4) * 8;               // + kstep*16
    const int b_row = wc * 64 + ((lane >> 4) << 3) + (lane & 7);  // + nip*16
    const int b_kc  = ((lane >> 3) & 1) * 8;         // + kstep*16

    for (int t = 0; t < NT; ++t) {
        const int buf = t & 1;
        if (t + 1 < NT) {
            issue_loads(t + 1, buf ^ 1);
            asm volatile("cp.async.wait_group 1;" ::: "memory");
        } else {
            asm volatile("cp.async.wait_group 0;" ::: "memory");
        }
        __syncthreads();

        const uint32_t baseA = sA0 + buf * bufStride;
        const uint32_t baseB = sB0 + buf * bufStride;

#pragma unroll
        for (int ks = 0; ks < 2; ++ks) {
            uint32_t af[2][4];
#pragma unroll
            for (int mi = 0; mi < 2; ++mi) {
                uint32_t addr = baseA +
                    (uint32_t)((a_row + mi * 16) * SROW + a_kc + ks * 16) * 2;
                asm volatile(
                    "ldmatrix.sync.aligned.m8n8.x4.shared.b16 {%0, %1, %2, %3}, [%4];"
                    : "=r"(af[mi][0]), "=r"(af[mi][1]), "=r"(af[mi][2]), "=r"(af[mi][3])
                    : "r"(addr));
            }
            uint32_t bf[8][2];
#pragma unroll
            for (int np = 0; np < 4; ++np) {   // pairs of n8
                uint32_t addr = baseB +
                    (uint32_t)((b_row + np * 16) * SROW + b_kc + ks * 16) * 2;
                uint32_t r0, r1, r2, r3;
                asm volatile(
                    "ldmatrix.sync.aligned.m8n8.x4.shared.b16 {%0, %1, %2, %3}, [%4];"
                    : "=r"(r0), "=r"(r1), "=r"(r2), "=r"(r3)
                    : "r"(addr));
                bf[2 * np][0] = r0; bf[2 * np][1] = r1;
                bf[2 * np + 1][0] = r2; bf[2 * np + 1][1] = r3;
            }
#pragma unroll
            for (int mi = 0; mi < 2; ++mi)
#pragma unroll
                for (int ni = 0; ni < 8; ++ni) {
                    asm volatile(
                        "mma.sync.aligned.m16n8k16.row.col.f32.bf16.bf16.f32 "
                        "{%0, %1, %2, %3}, {%4, %5, %6, %7}, {%8, %9}, "
                        "{%0, %1, %2, %3};"
                        : "+f"(acc[mi][ni][0]), "+f"(acc[mi][ni][1]),
                          "+f"(acc[mi][ni][2]), "+f"(acc[mi][ni][3])
                        : "r"(af[mi][0]), "r"(af[mi][1]),
                          "r"(af[mi][2]), "r"(af[mi][3]),
                          "r"(bf[ni][0]), "r"(bf[ni][1]));
                }
        }
        __syncthreads();
    }

    // epilogue: c fragment -> g_qkv (fp32)
    const int em = bm + wr * 32 + (lane >> 2);   // +mi*16, +8 for c2/c3
    const int en = bn + wc * 64 + (lane & 3) * 2;  // +ni*8
#pragma unroll
    for (int mi = 0; mi < 2; ++mi) {
#pragma unroll
        for (int ni = 0; ni < 8; ++ni) {
            int row0 = em + mi * 16;
            int col = en + ni * 8;
            *(float2*)&g_qkv[(size_t)row0 * EE + col] =
                make_float2(acc[mi][ni][0], acc[mi][ni][1]);
            *(float2*)&g_qkv[(size_t)(row0 + 8) * EE + col] =
                make_float2(acc[mi][ni][2], acc[mi][ni][3]);
        }
    }
}

// ---------------------------------------------------------------------------
// Kernel 2: sliding-window attention (unchanged, known-good).
// ---------------------------------------------------------------------------
#define SQ_STRIDE 36
#define SK_STRIDE 197
#define SAT_STRIDE 36

__global__ __launch_bounds__(512, 1)
void attn_kernel(float* __restrict__ out) {
    __shared__ float sSb[32 * 129];   // band scores: [i][w]
    __shared__ float sU[32 * SQ_STRIDE + 32 * SK_STRIDE];

    float* const sQ = sU;                              // [32 f][36]
    float* const sK = sU + 32 * SQ_STRIDE;             // [32 f][197]
    float* const sAttT = sU;                           // [160 r][36]

    const int tid = threadIdx.x;
    const int b   = blockIdx.y;
    const int q0  = blockIdx.x * 32;
    const float* base = g_qkv + (size_t)b * NN * EE;

    const int ig     = tid >> 6;     // 0..7 : i = 4*ig + a
    const int lane64 = tid & 63;     // r = lane64 + 64*j

    for (int idx = tid; idx < 32 * 32; idx += 512) {
        int f = idx >> 5;
        int r = 160 + (idx & 31);
        sK[f * SK_STRIDE + r] = 0.f;
    }

    float acc[4][3];
#pragma unroll
    for (int a = 0; a < 4; ++a)
#pragma unroll
        for (int j = 0; j < 3; ++j) acc[a][j] = 0.f;

    for (int f0 = 0; f0 < FF; f0 += 32) {
        if (tid < 256) {
            int row = tid >> 3;
            int c   = (tid & 7) << 2;
            float4 v = *(const float4*)&base[(q0 + row) * EE + f0 + c];
            sQ[(c + 0) * SQ_STRIDE + row] = v.x;
            sQ[(c + 1) * SQ_STRIDE + row] = v.y;
            sQ[(c + 2) * SQ_STRIDE + row] = v.z;
            sQ[(c + 3) * SQ_STRIDE + row] = v.w;
        }
#pragma unroll
        for (int it = 0; it < 3; ++it) {
            int idx = tid + it * 512;
            if (idx < 1280) {
                int row = idx >> 3;          // 0..159
                int c   = (idx & 7) << 2;
                int n   = q0 - 127 + row;
                float4 v = make_float4(0.f, 0.f, 0.f, 0.f);
                if (n >= 0 && n < NN)
                    v = *(const float4*)&base[n * EE + DD + f0 + c];
                sK[(c + 0) * SK_STRIDE + row] = v.x;
                sK[(c + 1) * SK_STRIDE + row] = v.y;
                sK[(c + 2) * SK_STRIDE + row] = v.z;
                sK[(c + 3) * SK_STRIDE + row] = v.w;
            }
        }
        __syncthreads();

#pragma unroll 4
        for (int f = 0; f < 32; ++f) {
            float4 qv = *(const float4*)&sQ[f * SQ_STRIDE + 4 * ig];
            float qa[4] = {qv.x, qv.y, qv.z, qv.w};
            float kv[3];
            kv[0] = sK[f * SK_STRIDE + lane64];
            kv[1] = sK[f * SK_STRIDE + lane64 + 64];
            kv[2] = sK[f * SK_STRIDE + lane64 + 128];
#pragma unroll
            for (int a = 0; a < 4; ++a)
#pragma unroll
                for (int j = 0; j < 3; ++j)
                    acc[a][j] = fmaf(qa[a], kv[j], acc[a][j]);
        }
        __syncthreads();
    }

#pragma unroll
    for (int a = 0; a < 4; ++a) {
        int i = 4 * ig + a;
#pragma unroll
        for (int j = 0; j < 3; ++j) {
            int r = lane64 + 64 * j;
            int w = r - i;
            if (w >= 0 && w < WW) sSb[i * 129 + w] = acc[a][j];
        }
    }
    __syncthreads();

    {
        const int wid  = tid >> 5;
        const int lane = tid & 31;
#pragma unroll
        for (int ii = 0; ii < 2; ++ii) {
            int i = 2 * wid + ii;
            float vals[4];
            float m = -CUDART_INF_F;
#pragma unroll
            for (int t = 0; t < 4; ++t) {
                vals[t] = sSb[i * 129 + lane + 32 * t];
                m = fmaxf(m, vals[t]);
            }
#pragma unroll
            for (int o = 16; o > 0; o >>= 1)
                m = fmaxf(m, __shfl_xor_sync(0xffffffffu, m, o));
            float s = 0.f;
#pragma unroll
            for (int t = 0; t < 4; ++t) s += __expf(vals[t] - m);
#pragma unroll
            for (int o = 16; o > 0; o >>= 1)
                s += __shfl_xor_sync(0xffffffffu, s, o);
            float inv = 1.f / s;
#pragma unroll
            for (int t = 0; t < 5; ++t) {
                int r = lane + 32 * t;
                int w = r - i;
                float val = 0.f;
                if (w >= 0 && w < WW)
                    val = __expf(sSb[i * 129 + w] - m) * inv;
                sAttT[r * SAT_STRIDE + i] = val;
            }
        }
    }
    __syncthreads();

    {
        const int ig2     = tid >> 7;    // 0..3 : i = 8*ig2 + a
        const int lane128 = tid & 127;   // d = 4*lane128
        const int d0 = 4 * lane128;
        const float* vbase = base + 2 * DD + d0;

        float4 o4[8];
#pragma unroll
        for (int a = 0; a < 8; ++a) o4[a] = make_float4(0.f, 0.f, 0.f, 0.f);

        const int rstart = (q0 < 127) ? (127 - q0) : 0;
#pragma unroll 2
        for (int r = rstart; r < 159; ++r) {
            int n = q0 - 127 + r;
            float4 av0 = *(const float4*)&sAttT[r * SAT_STRIDE + 8 * ig2];
            float4 av1 = *(const float4*)&sAttT[r * SAT_STRIDE + 8 * ig2 + 4];
            float4 vv = *(const float4*)&vbase[n * EE];
            float av[8] = {av0.x, av0.y, av0.z, av0.w, av1.x, av1.y, av1.z, av1.w};
#pragma unroll
            for (int a = 0; a < 8; ++a) {
                o4[a].x = fmaf(av[a], vv.x, o4[a].x);
                o4[a].y = fmaf(av[a], vv.y, o4[a].y);
                o4[a].z = fmaf(av[a], vv.z, o4[a].z);
                o4[a].w = fmaf(av[a], vv.w, o4[a].w);
            }
        }

#pragma unroll
        for (int a = 0; a < 8; ++a) {
            int row = q0 + 8 * ig2 + a;
            *(float4*)&out[((size_t)b * NN + row) * DD + d0] = o4[a];
        }
    }
}

extern "C" void kernel_launch(void* const* d_in, const int* in_sizes, int n_in,
                              void* d_out, int out_size) {
    const float* x  = (const float*)d_in[0];
    const float* wl = (const float*)d_in[1];
    float* out = (float*)d_out;

    const int nx4 = BB * NN * FF / 4;   // 524288
    const int nw4 = EE * FF / 4;        // 196608
    conv_x_kernel<<<(nx4 + 255) / 256, 256>>>(x);
    conv_w_kernel<<<(nw4 + 255) / 256, 256>>>(wl);

    dim3 g1(EE / 128, (BB * NN) / 128);   // 12 x 32
    qkv_mma_kernel<<<g1, 256>>>();

    dim3 g2(NN / 32, BB);                 // 64 x 2
    attn_kernel<<<g2, 512>>>(out);
}

// round 10
// speedup vs baseline: 1.8988x; 1.3684x over previous
#include <cuda_runtime.h>
#include <cuda_bf16.h>
#include <math_constants.h>
#include <cstdint>

#define BB 2
#define NN 2048
#define FF 512
#define DD 512
#define EE 1536   // 3*DD
#define WW 128

// scratch buffers: qkv as bf16 hi/lo split
__device__ __nv_bfloat16 g_qh[BB * NN * EE];
__device__ __nv_bfloat16 g_ql[BB * NN * EE];
__device__ __nv_bfloat16 g_xhi[BB * NN * FF];
__device__ __nv_bfloat16 g_xlo[BB * NN * FF];
__device__ __nv_bfloat16 g_whi[EE * FF];
__device__ __nv_bfloat16 g_wlo[EE * FF];

__device__ __forceinline__ uint32_t smem_u32(const void* p) {
    uint32_t a;
    asm("{ .reg .u64 t; cvta.to.shared.u64 t, %1; cvt.u32.u64 %0, t; }"
        : "=r"(a) : "l"(p));
    return a;
}

__device__ __forceinline__ void cp16(uint32_t dst, const void* src, bool valid) {
    int sz = valid ? 16 : 0;
    asm volatile("cp.async.cg.shared.global [%0], [%1], 16, %2;"
                 :: "r"(dst), "l"(src), "r"(sz) : "memory");
}

#define LDMX4(r0, r1, r2, r3, addr) \
    asm volatile("ldmatrix.sync.aligned.m8n8.x4.shared.b16 {%0, %1, %2, %3}, [%4];" \
                 : "=r"(r0), "=r"(r1), "=r"(r2), "=r"(r3) : "r"(addr))

#define LDMX4T(r0, r1, r2, r3, addr) \
    asm volatile("ldmatrix.sync.aligned.m8n8.x4.trans.shared.b16 {%0, %1, %2, %3}, [%4];" \
                 : "=r"(r0), "=r"(r1), "=r"(r2), "=r"(r3) : "r"(addr))

#define MMA16816(acc, a, b0, b1) \
    asm volatile("mma.sync.aligned.m16n8k16.row.col.f32.bf16.bf16.f32 " \
                 "{%0, %1, %2, %3}, {%4, %5, %6, %7}, {%8, %9}, {%0, %1, %2, %3};" \
                 : "+f"((acc)[0]), "+f"((acc)[1]), "+f"((acc)[2]), "+f"((acc)[3]) \
                 : "r"((a)[0]), "r"((a)[1]), "r"((a)[2]), "r"((a)[3]), \
                   "r"(b0), "r"(b1))

// ---------------------------------------------------------------------------
// Conversion: fp32 -> (bf16 hi, bf16 lo)
// ---------------------------------------------------------------------------
__device__ __forceinline__ void split4(const float* __restrict__ src, int i,
                                       __nv_bfloat16* __restrict__ hi,
                                       __nv_bfloat16* __restrict__ lo) {
    float4 v = ((const float4*)src)[i];
    __nv_bfloat16 h0 = __float2bfloat16_rn(v.x);
    __nv_bfloat16 h1 = __float2bfloat16_rn(v.y);
    __nv_bfloat16 h2 = __float2bfloat16_rn(v.z);
    __nv_bfloat16 h3 = __float2bfloat16_rn(v.w);
    __nv_bfloat16 l0 = __float2bfloat16_rn(v.x - __bfloat162float(h0));
    __nv_bfloat16 l1 = __float2bfloat16_rn(v.y - __bfloat162float(h1));
    __nv_bfloat16 l2 = __float2bfloat16_rn(v.z - __bfloat162float(h2));
    __nv_bfloat16 l3 = __float2bfloat16_rn(v.w - __bfloat162float(h3));
    __nv_bfloat162* hp = (__nv_bfloat162*)hi;
    __nv_bfloat162* lp = (__nv_bfloat162*)lo;
    hp[2 * i]     = __nv_bfloat162{h0, h1};
    hp[2 * i + 1] = __nv_bfloat162{h2, h3};
    lp[2 * i]     = __nv_bfloat162{l0, l1};
    lp[2 * i + 1] = __nv_bfloat162{l2, l3};
}

__global__ void conv_x_kernel(const float* __restrict__ src) {
    int i = blockIdx.x * blockDim.x + threadIdx.x;
    if (i < BB * NN * FF / 4) split4(src, i, g_xhi, g_xlo);
}
__global__ void conv_w_kernel(const float* __restrict__ src) {
    int i = blockIdx.x * blockDim.x + threadIdx.x;
    if (i < EE * FF / 4) split4(src, i, g_whi, g_wlo);
}

// ---------------------------------------------------------------------------
// Kernel 1: QKV GEMM via mma.sync bf16 (split-bf16, 3 passes).
// Epilogue writes qkv as bf16 hi/lo (g_qh/g_ql).
// ---------------------------------------------------------------------------
#define BK 32
#define SROW 40

__global__ __launch_bounds__(256, 2)
void qkv_mma_kernel() {
    __shared__ __nv_bfloat16 sA[2][128 * SROW];
    __shared__ __nv_bfloat16 sB[2][128 * SROW];

    const int tid = threadIdx.x;
    const int lane = tid & 31;
    const int wid = tid >> 5;
    const int wr = wid & 3;
    const int wc = wid >> 2;
    const int bn = blockIdx.x * 128;
    const int bm = blockIdx.y * 128;
    const int c0 = tid * 2;

    float acc[2][8][4];
#pragma unroll
    for (int mi = 0; mi < 2; ++mi)
#pragma unroll
        for (int ni = 0; ni < 8; ++ni)
#pragma unroll
            for (int q = 0; q < 4; ++q) acc[mi][ni][q] = 0.f;

    const __nv_bfloat16* APs[3] = {g_xhi, g_xhi, g_xlo};
    const __nv_bfloat16* BPs[3] = {g_whi, g_wlo, g_whi};
    const int NT = 48;

    const uint32_t sA0 = smem_u32(sA[0]);
    const uint32_t sB0 = smem_u32(sB[0]);
    const uint32_t bufStride = 128 * SROW * 2;

    auto issue_loads = [&](int t, int buf) {
        int pass = t >> 4;
        int k0 = (t & 15) * BK;
        const __nv_bfloat16* A = APs[pass] + (size_t)bm * FF + k0;
        const __nv_bfloat16* B = BPs[pass] + (size_t)bn * FF + k0;
#pragma unroll
        for (int j = 0; j < 2; ++j) {
            int c = c0 + j;
            int row = c >> 2;
            int col = (c & 3) * 8;
            uint32_t da = sA0 + buf * bufStride + (uint32_t)(row * SROW + col) * 2;
            uint32_t db = sB0 + buf * bufStride + (uint32_t)(row * SROW + col) * 2;
            asm volatile("cp.async.cg.shared.global [%0], [%1], 16;"
                         :: "r"(da), "l"(A + row * FF + col) : "memory");
            asm volatile("cp.async.cg.shared.global [%0], [%1], 16;"
                         :: "r"(db), "l"(B + row * FF + col) : "memory");
        }
        asm volatile("cp.async.commit_group;" ::: "memory");
    };

    issue_loads(0, 0);

    const int a_row = wr * 32 + (lane & 15);
    const int a_kc  = (lane >> 4) * 8;
    const int b_row = wc * 64 + ((lane >> 4) << 3) + (lane & 7);
    const int b_kc  = ((lane >> 3) & 1) * 8;

    for (int t = 0; t < NT; ++t) {
        const int buf = t & 1;
        if (t + 1 < NT) {
            issue_loads(t + 1, buf ^ 1);
            asm volatile("cp.async.wait_group 1;" ::: "memory");
        } else {
            asm volatile("cp.async.wait_group 0;" ::: "memory");
        }
        __syncthreads();

        const uint32_t baseA = sA0 + buf * bufStride;
        const uint32_t baseB = sB0 + buf * bufStride;

#pragma unroll
        for (int ks = 0; ks < 2; ++ks) {
            uint32_t af[2][4];
#pragma unroll
            for (int mi = 0; mi < 2; ++mi) {
                uint32_t addr = baseA +
                    (uint32_t)((a_row + mi * 16) * SROW + a_kc + ks * 16) * 2;
                LDMX4(af[mi][0], af[mi][1], af[mi][2], af[mi][3], addr);
            }
            uint32_t bf[8][2];
#pragma unroll
            for (int np = 0; np < 4; ++np) {
                uint32_t addr = baseB +
                    (uint32_t)((b_row + np * 16) * SROW + b_kc + ks * 16) * 2;
                uint32_t r0, r1, r2, r3;
                LDMX4(r0, r1, r2, r3, addr);
                bf[2 * np][0] = r0; bf[2 * np][1] = r1;
                bf[2 * np + 1][0] = r2; bf[2 * np + 1][1] = r3;
            }
#pragma unroll
            for (int mi = 0; mi < 2; ++mi)
#pragma unroll
                for (int ni = 0; ni < 8; ++ni)
                    MMA16816(acc[mi][ni], af[mi], bf[ni][0], bf[ni][1]);
        }
        __syncthreads();
    }

    // epilogue: acc -> bf16 hi/lo
    const int em = bm + wr * 32 + (lane >> 2);
    const int en = bn + wc * 64 + (lane & 3) * 2;
#pragma unroll
    for (int mi = 0; mi < 2; ++mi) {
#pragma unroll
        for (int ni = 0; ni < 8; ++ni) {
#pragma unroll
            for (int half = 0; half < 2; ++half) {
                int row = em + mi * 16 + half * 8;
                int col = en + ni * 8;
                float v0 = acc[mi][ni][2 * half], v1 = acc[mi][ni][2 * half + 1];
                __nv_bfloat16 h0 = __float2bfloat16_rn(v0);
                __nv_bfloat16 h1 = __float2bfloat16_rn(v1);
                __nv_bfloat16 l0 = __float2bfloat16_rn(v0 - __bfloat162float(h0));
                __nv_bfloat16 l1 = __float2bfloat16_rn(v1 - __bfloat162float(h1));
                *(__nv_bfloat162*)&g_qh[(size_t)row * EE + col] = __nv_bfloat162{h0, h1};
                *(__nv_bfloat162*)&g_ql[(size_t)row * EE + col] = __nv_bfloat162{l0, l1};
            }
        }
    }
}

// ---------------------------------------------------------------------------
// Kernel 2: sliding-window attention via mma.sync bf16 (split hi/lo).
// 32 queries/CTA, 256 threads (8 warps), grid (64, 2).
// Phase A: S[32][192] = Q.K^T (warps 2Mx4N, n48 each), zero-pad via zfill.
// Softmax over band w=r-i in [0,128); P stored bf16 hi/lo in smem.
// Phase B: out[32][512] = P.V (warps 2Mx4N, n128 each), V via ldmatrix.trans.
// ---------------------------------------------------------------------------
// dynamic smem layout (bytes):
#define SM_QH(buf)  ((buf) * 64512 + 0)
#define SM_QL(buf)  ((buf) * 64512 + 4608)
#define SM_KH(buf)  ((buf) * 64512 + 9216)
#define SM_KL(buf)  ((buf) * 64512 + 36864)
#define SM_VH(buf)  ((buf) * 66560 + 0)
#define SM_VL(buf)  ((buf) * 66560 + 33280)
#define SM_S        133120
#define SM_PH       158208
#define SM_PL       171008
#define SMEM_ATTN   183808
// strides (bf16 elements)
#define QK_STR 72
#define V_STR  520
#define P_STR  200
#define S_STR  196

extern __shared__ char dynsm[];

__global__ __launch_bounds__(256, 1)
void attn_tc_kernel(float* __restrict__ out) {
    const int tid = threadIdx.x;
    const int lane = tid & 31;
    const int wid = tid >> 5;
    const int wr = wid & 1;      // M group (16 rows)
    const int wc = wid >> 1;     // N group
    const int b  = blockIdx.y;
    const int q0 = blockIdx.x * 32;
    const int bbase = b * NN;

    const uint32_t sm = smem_u32(dynsm);
    float* const sS = (float*)(dynsm + SM_S);
    __nv_bfloat16* const sPh = (__nv_bfloat16*)(dynsm + SM_PH);
    __nv_bfloat16* const sPl = (__nv_bfloat16*)(dynsm + SM_PL);

    // ---------------- Phase A loads ----------------
    // K tile: 192 rows x 64 cols = 1536 16B-chunks (8 chunks/row).
    // Q tile: 32 rows x 64 cols = 256 chunks.  hi+lo both per chunk.
    auto issueA = [&](int c, int buf) {
        int k0 = c * 64;
#pragma unroll
        for (int j = 0; j < 6; ++j) {
            int id = tid + j * 256;          // 0..1535
            int row = id >> 3, cc = id & 7;
            int n = q0 - 127 + row;
            bool valid = (row < 160) && (n >= 0) && (n < NN);
            size_t gidx = ((size_t)(bbase + (valid ? n : 0))) * EE + DD + k0 + cc * 8;
            uint32_t doff = (uint32_t)(row * QK_STR + cc * 8) * 2;
            cp16(sm + SM_KH(buf) + doff, g_qh + gidx, valid);
            cp16(sm + SM_KL(buf) + doff, g_ql + gidx, valid);
        }
        {
            int row = tid >> 3, cc = tid & 7;
            size_t gidx = ((size_t)(bbase + q0 + row)) * EE + k0 + cc * 8;
            uint32_t doff = (uint32_t)(row * QK_STR + cc * 8) * 2;
            cp16(sm + SM_QH(buf) + doff, g_qh + gidx, true);
            cp16(sm + SM_QL(buf) + doff, g_ql + gidx, true);
        }
        asm volatile("cp.async.commit_group;" ::: "memory");
    };

    auto issueV = [&](int c, int buf) {
        int r0 = c * 32;
#pragma unroll
        for (int j = 0; j < 8; ++j) {
            int id = tid + j * 256;          // 0..2047
            int row = id >> 6, cc = id & 63;
            int n = q0 - 127 + r0 + row;
            bool valid = (n >= 0) && (n < NN);
            size_t gidx = ((size_t)(bbase + (valid ? n : 0))) * EE + 2 * DD + cc * 8;
            uint32_t doff = (uint32_t)(row * V_STR + cc * 8) * 2;
            cp16(sm + SM_VH(buf) + doff, g_qh + gidx, valid);
            cp16(sm + SM_VL(buf) + doff, g_ql + gidx, valid);
        }
        asm volatile("cp.async.commit_group;" ::: "memory");
    };

    // ---------------- Phase A: S = Q.K^T ----------------
    float accA[6][4];
#pragma unroll
    for (int ni = 0; ni < 6; ++ni)
#pragma unroll
        for (int q = 0; q < 4; ++q) accA[ni][q] = 0.f;

    const int a_row = wr * 16 + (lane & 15);
    const int a_kc  = (lane >> 4) * 8;
    const int bA_row = wc * 48 + ((lane >> 4) << 3) + (lane & 7);
    const int bA_kc  = ((lane >> 3) & 1) * 8;

    issueA(0, 0);
    for (int c = 0; c < 8; ++c) {
        const int buf = c & 1;
        if (c < 7) {
            issueA(c + 1, buf ^ 1);
            asm volatile("cp.async.wait_group 1;" ::: "memory");
        } else {
            asm volatile("cp.async.wait_group 0;" ::: "memory");
        }
        __syncthreads();

#pragma unroll
        for (int ks = 0; ks < 4; ++ks) {
            uint32_t ah[4], al[4];
            LDMX4(ah[0], ah[1], ah[2], ah[3],
                  sm + SM_QH(buf) + (uint32_t)(a_row * QK_STR + a_kc + ks * 16) * 2);
            LDMX4(al[0], al[1], al[2], al[3],
                  sm + SM_QL(buf) + (uint32_t)(a_row * QK_STR + a_kc + ks * 16) * 2);
            uint32_t bh[6][2], bl[6][2];
#pragma unroll
            for (int np = 0; np < 3; ++np) {
                uint32_t off = (uint32_t)((bA_row + np * 16) * QK_STR + bA_kc + ks * 16) * 2;
                uint32_t r0, r1, r2, r3;
                LDMX4(r0, r1, r2, r3, sm + SM_KH(buf) + off);
                bh[2 * np][0] = r0; bh[2 * np][1] = r1;
                bh[2 * np + 1][0] = r2; bh[2 * np + 1][1] = r3;
                LDMX4(r0, r1, r2, r3, sm + SM_KL(buf) + off);
                bl[2 * np][0] = r0; bl[2 * np][1] = r1;
                bl[2 * np + 1][0] = r2; bl[2 * np + 1][1] = r3;
            }
#pragma unroll
            for (int ni = 0; ni < 6; ++ni) {
                MMA16816(accA[ni], ah, bh[ni][0], bh[ni][1]);
                MMA16816(accA[ni], ah, bl[ni][0], bl[ni][1]);
                MMA16816(accA[ni], al, bh[ni][0], bh[ni][1]);
            }
        }
        __syncthreads();
    }

    // write S to smem
#pragma unroll
    for (int ni = 0; ni < 6; ++ni) {
        int row = wr * 16 + (lane >> 2);
        int col = wc * 48 + ni * 8 + (lane & 3) * 2;
        sS[row * S_STR + col] = accA[ni][0];
        sS[row * S_STR + col + 1] = accA[ni][1];
        sS[(row + 8) * S_STR + col] = accA[ni][2];
        sS[(row + 8) * S_STR + col + 1] = accA[ni][3];
    }

    // prefetch V chunks 0,1 (Phase A buffers free after last sync)
    issueV(0, 0);
    issueV(1, 1);
    __syncthreads();

    // ---------------- softmax over band ----------------
#pragma unroll
    for (int ii = 0; ii < 4; ++ii) {
        int i = wid * 4 + ii;
        float vals[4];
        float m = -CUDART_INF_F;
#pragma unroll
        for (int t = 0; t < 4; ++t) {
            vals[t] = sS[i * S_STR + i + lane + 32 * t];
            m = fmaxf(m, vals[t]);
        }
#pragma unroll
        for (int o = 16; o > 0; o >>= 1)
            m = fmaxf(m, __shfl_xor_sync(0xffffffffu, m, o));
        float s = 0.f;
#pragma unroll
        for (int t = 0; t < 4; ++t) s += __expf(vals[t] - m);
#pragma unroll
        for (int o = 16; o > 0; o >>= 1)
            s += __shfl_xor_sync(0xffffffffu, s, o);
        float inv = 1.f / s;
#pragma unroll
        for (int t = 0; t < 6; ++t) {
            int r = lane + 32 * t;
            int w = r - i;
            float val = (w >= 0 && w < WW) ? __expf(sS[i * S_STR + r] - m) * inv : 0.f;
            __nv_bfloat16 h = __float2bfloat16_rn(val);
            __nv_bfloat16 l = __float2bfloat16_rn(val - __bfloat162float(h));
            sPh[i * P_STR + r] = h;
            sPl[i * P_STR + r] = l;
        }
    }
    __syncthreads();

    // ---------------- Phase B: out = P.V ----------------
    float accO[16][4];
#pragma unroll
    for (int ni = 0; ni < 16; ++ni)
#pragma unroll
        for (int q = 0; q < 4; ++q) accO[ni][q] = 0.f;

    const int pa_row = wr * 16 + (lane & 15);
    const int v_row  = (lane & 15);
    const int v_col0 = wc * 128 + ((lane >> 4) << 3);

    for (int c = 0; c < 6; ++c) {
        if (c < 5) asm volatile("cp.async.wait_group 1;" ::: "memory");
        else       asm volatile("cp.async.wait_group 0;" ::: "memory");
        __syncthreads();
        const int buf = c & 1;

#pragma unroll
        for (int ks = 0; ks < 2; ++ks) {
            int kg = c * 32 + ks * 16;
            uint32_t ph[4], pl[4];
            LDMX4(ph[0], ph[1], ph[2], ph[3],
                  sm + SM_PH + (uint32_t)(pa_row * P_STR + kg + (lane >> 4) * 8) * 2);
            LDMX4(pl[0], pl[1], pl[2], pl[3],
                  sm + SM_PL + (uint32_t)(pa_row * P_STR + kg + (lane >> 4) * 8) * 2);
#pragma unroll
            for (int nt = 0; nt < 8; ++nt) {
                uint32_t off = (uint32_t)((ks * 16 + v_row) * V_STR + v_col0 + nt * 16) * 2;
                uint32_t h0, h1, h2, h3, l0, l1, l2, l3;
                LDMX4T(h0, h1, h2, h3, sm + SM_VH(buf) + off);
                LDMX4T(l0, l1, l2, l3, sm + SM_VL(buf) + off);
                MMA16816(accO[2 * nt], ph, h0, h1);
                MMA16816(accO[2 * nt + 1], ph, h2, h3);
                MMA16816(accO[2 * nt], ph, l0, l1);
                MMA16816(accO[2 * nt + 1], ph, l2, l3);
                MMA16816(accO[2 * nt], pl, h0, h1);
                MMA16816(accO[2 * nt + 1], pl, h2, h3);
            }
        }
        __syncthreads();
        if (c + 2 < 6) issueV(c + 2, buf);
    }

    // epilogue -> out fp32
    const int orow = q0 + wr * 16 + (lane >> 2);
    const int ocol = wc * 128 + (lane & 3) * 2;
#pragma unroll
    for (int ni = 0; ni < 16; ++ni) {
        int col = ocol + ni * 8;
        *(float2*)&out[((size_t)(bbase + orow)) * DD + col] =
            make_float2(accO[ni][0], accO[ni][1]);
        *(float2*)&out[((size_t)(bbase + orow + 8)) * DD + col] =
            make_float2(accO[ni][2], accO[ni][3]);
    }
}

extern "C" void kernel_launch(void* const* d_in, const int* in_sizes, int n_in,
                              void* d_out, int out_size) {
    const float* x  = (const float*)d_in[0];
    const float* wl = (const float*)d_in[1];
    float* out = (float*)d_out;

    cudaFuncSetAttribute(attn_tc_kernel,
                         cudaFuncAttributeMaxDynamicSharedMemorySize, SMEM_ATTN);

    const int nx4 = BB * NN * FF / 4;
    const int nw4 = EE * FF / 4;
    conv_x_kernel<<<(nx4 + 255) / 256, 256>>>(x);
    conv_w_kernel<<<(nw4 + 255) / 256, 256>>>(wl);

    dim3 g1(EE / 128, (BB * NN) / 128);   // 12 x 32
    qkv_mma_kernel<<<g1, 256>>>();

    dim3 g2(NN / 32, BB);                 // 64 x 2
    attn_tc_kernel<<<g2, 256, SMEM_ATTN>>>(out);
}

// round 12
// speedup vs baseline: 2.4880x; 1.3103x over previous
#include <cuda_runtime.h>
#include <cuda_bf16.h>
#include <math_constants.h>
#include <cstdint>

#define BB 2
#define NN 2048
#define FF 512
#define DD 512
#define EE 1536   // 3*DD
#define WW 128

// scratch buffers: qkv as bf16 hi/lo split
__device__ __nv_bfloat16 g_qh[BB * NN * EE];
__device__ __nv_bfloat16 g_ql[BB * NN * EE];
__device__ __nv_bfloat16 g_xhi[BB * NN * FF];
__device__ __nv_bfloat16 g_xlo[BB * NN * FF];
__device__ __nv_bfloat16 g_whi[EE * FF];
__device__ __nv_bfloat16 g_wlo[EE * FF];

__device__ __forceinline__ uint32_t smem_u32(const void* p) {
    uint32_t a;
    asm("{ .reg .u64 t; cvta.to.shared.u64 t, %1; cvt.u32.u64 %0, t; }"
        : "=r"(a) : "l"(p));
    return a;
}

__device__ __forceinline__ void cp16(uint32_t dst, const void* src, bool valid) {
    int sz = valid ? 16 : 0;
    asm volatile("cp.async.cg.shared.global [%0], [%1], 16, %2;"
                 :: "r"(dst), "l"(src), "r"(sz) : "memory");
}

#define LDMX4(r0, r1, r2, r3, addr) \
    asm volatile("ldmatrix.sync.aligned.m8n8.x4.shared.b16 {%0, %1, %2, %3}, [%4];" \
                 : "=r"(r0), "=r"(r1), "=r"(r2), "=r"(r3) : "r"(addr))

#define LDMX4T(r0, r1, r2, r3, addr) \
    asm volatile("ldmatrix.sync.aligned.m8n8.x4.trans.shared.b16 {%0, %1, %2, %3}, [%4];" \
                 : "=r"(r0), "=r"(r1), "=r"(r2), "=r"(r3) : "r"(addr))

#define MMA16816(acc, a, b0, b1) \
    asm volatile("mma.sync.aligned.m16n8k16.row.col.f32.bf16.bf16.f32 " \
                 "{%0, %1, %2, %3}, {%4, %5, %6, %7}, {%8, %9}, {%0, %1, %2, %3};" \
                 : "+f"((acc)[0]), "+f"((acc)[1]), "+f"((acc)[2]), "+f"((acc)[3]) \
                 : "r"((a)[0]), "r"((a)[1]), "r"((a)[2]), "r"((a)[3]), \
                   "r"(b0), "r"(b1))

// ---------------------------------------------------------------------------
// Conversion: fp32 -> (bf16 hi, bf16 lo)
// ---------------------------------------------------------------------------
__device__ __forceinline__ void split4(const float* __restrict__ src, int i,
                                       __nv_bfloat16* __restrict__ hi,
                                       __nv_bfloat16* __restrict__ lo) {
    float4 v = ((const float4*)src)[i];
    __nv_bfloat16 h0 = __float2bfloat16_rn(v.x);
    __nv_bfloat16 h1 = __float2bfloat16_rn(v.y);
    __nv_bfloat16 h2 = __float2bfloat16_rn(v.z);
    __nv_bfloat16 h3 = __float2bfloat16_rn(v.w);
    __nv_bfloat16 l0 = __float2bfloat16_rn(v.x - __bfloat162float(h0));
    __nv_bfloat16 l1 = __float2bfloat16_rn(v.y - __bfloat162float(h1));
    __nv_bfloat16 l2 = __float2bfloat16_rn(v.z - __bfloat162float(h2));
    __nv_bfloat16 l3 = __float2bfloat16_rn(v.w - __bfloat162float(h3));
    __nv_bfloat162* hp = (__nv_bfloat162*)hi;
    __nv_bfloat162* lp = (__nv_bfloat162*)lo;
    hp[2 * i]     = __nv_bfloat162{h0, h1};
    hp[2 * i + 1] = __nv_bfloat162{h2, h3};
    lp[2 * i]     = __nv_bfloat162{l0, l1};
    lp[2 * i + 1] = __nv_bfloat162{l2, l3};
}

__global__ void conv_x_kernel(const float* __restrict__ src) {
    int i = blockIdx.x * blockDim.x + threadIdx.x;
    if (i < BB * NN * FF / 4) split4(src, i, g_xhi, g_xlo);
}
__global__ void conv_w_kernel(const float* __restrict__ src) {
    int i = blockIdx.x * blockDim.x + threadIdx.x;
    if (i < EE * FF / 4) split4(src, i, g_whi, g_wlo);
}

// ---------------------------------------------------------------------------
// Kernel 1: QKV GEMM, fused split-bf16: per k-tile load Ahi/Alo/Bhi/Blo once,
// accumulate Xhi.Whi + Xhi.Wlo + Xlo.Whi in one loop (16 k-tiles of 32).
// CTA tile 128x128, 8 warps (4Mx2N), warp tile 32x64.
// Epilogue staged through smem for 16B-coalesced hi/lo stores.
// Dynamic smem: 4 arrays x 2 buffers x (128*SROW) bf16 = 80KB.
// ---------------------------------------------------------------------------
#define BK 32
#define SROW 40
#define QBUF (128 * SROW * 2)          // 10240 B per buffer
#define SM_AH(buf) ((buf) * QBUF)
#define SM_AL(buf) (20480 + (buf) * QBUF)
#define SM_BH(buf) (40960 + (buf) * QBUF)
#define SM_BL(buf) (61440 + (buf) * QBUF)
#define SMEM_QKV 81920

extern __shared__ char dynsm[];

__global__ __launch_bounds__(256, 2)
void qkv_mma_kernel() {
    const int tid = threadIdx.x;
    const int lane = tid & 31;
    const int wid = tid >> 5;
    const int wr = wid & 3;
    const int wc = wid >> 2;
    const int bn = blockIdx.x * 128;
    const int bm = blockIdx.y * 128;

    const uint32_t sm = smem_u32(dynsm);

    float acc[2][8][4];
#pragma unroll
    for (int mi = 0; mi < 2; ++mi)
#pragma unroll
        for (int ni = 0; ni < 8; ++ni)
#pragma unroll
            for (int q = 0; q < 4; ++q) acc[mi][ni][q] = 0.f;

    // loads: 2048 chunks of 16B per stage (4 arrays x 128 rows x 4 chunks)
    auto issue_loads = [&](int t, int buf) {
        int k0 = t * BK;
#pragma unroll
        for (int j = 0; j < 8; ++j) {
            int id = tid + j * 256;          // 0..2047
            int arr = id >> 9;               // 0..3
            int cid = id & 511;
            int row = cid >> 2;
            int col = (cid & 3) * 8;
            uint32_t doff = (uint32_t)(row * SROW + col) * 2;
            const __nv_bfloat16* gp;
            uint32_t base;
            if (arr == 0)      { gp = g_xhi + (size_t)(bm + row) * FF + k0 + col; base = SM_AH(buf); }
            else if (arr == 1) { gp = g_xlo + (size_t)(bm + row) * FF + k0 + col; base = SM_AL(buf); }
            else if (arr == 2) { gp = g_whi + (size_t)(bn + row) * FF + k0 + col; base = SM_BH(buf); }
            else               { gp = g_wlo + (size_t)(bn + row) * FF + k0 + col; base = SM_BL(buf); }
            cp16(sm + base + doff, gp, true);
        }
        asm volatile("cp.async.commit_group;" ::: "memory");
    };

    issue_loads(0, 0);

    const int a_row = wr * 32 + (lane & 15);
    const int a_kc  = (lane >> 4) * 8;
    const int b_row = wc * 64 + ((lane >> 4) << 3) + (lane & 7);
    const int b_kc  = ((lane >> 3) & 1) * 8;

    for (int t = 0; t < 16; ++t) {
        const int buf = t & 1;
        if (t + 1 < 16) {
            issue_loads(t + 1, buf ^ 1);
            asm volatile("cp.async.wait_group 1;" ::: "memory");
        } else {
            asm volatile("cp.async.wait_group 0;" ::: "memory");
        }
        __syncthreads();

#pragma unroll
        for (int ks = 0; ks < 2; ++ks) {
            uint32_t ah[2][4], al[2][4];
#pragma unroll
            for (int mi = 0; mi < 2; ++mi) {
                uint32_t off = (uint32_t)((a_row + mi * 16) * SROW + a_kc + ks * 16) * 2;
                LDMX4(ah[mi][0], ah[mi][1], ah[mi][2], ah[mi][3], sm + SM_AH(buf) + off);
                LDMX4(al[mi][0], al[mi][1], al[mi][2], al[mi][3], sm + SM_AL(buf) + off);
            }
#pragma unroll
            for (int np = 0; np < 4; ++np) {
                uint32_t off = (uint32_t)((b_row + np * 16) * SROW + b_kc + ks * 16) * 2;
                uint32_t h0, h1, h2, h3, l0, l1, l2, l3;
                LDMX4(h0, h1, h2, h3, sm + SM_BH(buf) + off);
                LDMX4(l0, l1, l2, l3, sm + SM_BL(buf) + off);
#pragma unroll
                for (int mi = 0; mi < 2; ++mi) {
                    MMA16816(acc[mi][2 * np],     ah[mi], h0, h1);
                    MMA16816(acc[mi][2 * np + 1], ah[mi], h2, h3);
                    MMA16816(acc[mi][2 * np],     ah[mi], l0, l1);
                    MMA16816(acc[mi][2 * np + 1], ah[mi], l2, l3);
                    MMA16816(acc[mi][2 * np],     al[mi], h0, h1);
                    MMA16816(acc[mi][2 * np + 1], al[mi], h2, h3);
                }
            }
        }
        __syncthreads();
    }

    // ---- epilogue: stage hi/lo bf16 in smem, then coalesced 16B stores ----
    __nv_bfloat16* const sOutH = (__nv_bfloat16*)dynsm;            // 32KB
    __nv_bfloat16* const sOutL = (__nv_bfloat16*)(dynsm + 32768);  // 32KB

    const int em = wr * 32 + (lane >> 2);
    const int en = wc * 64 + (lane & 3) * 2;
#pragma unroll
    for (int mi = 0; mi < 2; ++mi) {
#pragma unroll
        for (int ni = 0; ni < 8; ++ni) {
#pragma unroll
            for (int half = 0; half < 2; ++half) {
                int row = em + mi * 16 + half * 8;
                int col = en + ni * 8;
                float v0 = acc[mi][ni][2 * half], v1 = acc[mi][ni][2 * half + 1];
                __nv_bfloat16 h0 = __float2bfloat16_rn(v0);
                __nv_bfloat16 h1 = __float2bfloat16_rn(v1);
                __nv_bfloat16 l0 = __float2bfloat16_rn(v0 - __bfloat162float(h0));
                __nv_bfloat16 l1 = __float2bfloat16_rn(v1 - __bfloat162float(h1));
                *(__nv_bfloat162*)&sOutH[row * 128 + col] = __nv_bfloat162{h0, h1};
                *(__nv_bfloat162*)&sOutL[row * 128 + col] = __nv_bfloat162{l0, l1};
            }
        }
    }
    __syncthreads();

#pragma unroll
    for (int j = 0; j < 8; ++j) {
        int id = tid + j * 256;          // 0..2047
        int row = id >> 4;
        int c16 = id & 15;
        uint4 v = *(uint4*)&sOutH[row * 128 + c16 * 8];
        *(uint4*)&g_qh[(size_t)(bm + row) * EE + bn + c16 * 8] = v;
    }
#pragma unroll
    for (int j = 0; j < 8; ++j) {
        int id = tid + j * 256;
        int row = id >> 4;
        int c16 = id & 15;
        uint4 v = *(uint4*)&sOutL[row * 128 + c16 * 8];
        *(uint4*)&g_ql[(size_t)(bm + row) * EE + bn + c16 * 8] = v;
    }
}

// ---------------------------------------------------------------------------
// Kernel 2: sliding-window attention via mma.sync bf16 (unchanged from R10).
// ---------------------------------------------------------------------------
#define SM_QH(buf)  ((buf) * 64512 + 0)
#define SM_QL(buf)  ((buf) * 64512 + 4608)
#define SM_KH(buf)  ((buf) * 64512 + 9216)
#define SM_KL(buf)  ((buf) * 64512 + 36864)
#define SM_VH(buf)  ((buf) * 66560 + 0)
#define SM_VL(buf)  ((buf) * 66560 + 33280)
#define SM_S        133120
#define SM_PH       158208
#define SM_PL       171008
#define SMEM_ATTN   183808
#define QK_STR 72
#define V_STR  520
#define P_STR  200
#define S_STR  196

__global__ __launch_bounds__(256, 1)
void attn_tc_kernel(float* __restrict__ out) {
    const int tid = threadIdx.x;
    const int lane = tid & 31;
    const int wid = tid >> 5;
    const int wr = wid & 1;
    const int wc = wid >> 1;
    const int b  = blockIdx.y;
    const int q0 = blockIdx.x * 32;
    const int bbase = b * NN;

    const uint32_t sm = smem_u32(dynsm);
    float* const sS = (float*)(dynsm + SM_S);
    __nv_bfloat16* const sPh = (__nv_bfloat16*)(dynsm + SM_PH);
    __nv_bfloat16* const sPl = (__nv_bfloat16*)(dynsm + SM_PL);

    auto issueA = [&](int c, int buf) {
        int k0 = c * 64;
#pragma unroll
        for (int j = 0; j < 6; ++j) {
            int id = tid + j * 256;
            int row = id >> 3, cc = id & 7;
            int n = q0 - 127 + row;
            bool valid = (row < 160) && (n >= 0) && (n < NN);
            size_t gidx = ((size_t)(bbase + (valid ? n : 0))) * EE + DD + k0 + cc * 8;
            uint32_t doff = (uint32_t)(row * QK_STR + cc * 8) * 2;
            cp16(sm + SM_KH(buf) + doff, g_qh + gidx, valid);
            cp16(sm + SM_KL(buf) + doff, g_ql + gidx, valid);
        }
        {
            int row = tid >> 3, cc = tid & 7;
            size_t gidx = ((size_t)(bbase + q0 + row)) * EE + k0 + cc * 8;
            uint32_t doff = (uint32_t)(row * QK_STR + cc * 8) * 2;
            cp16(sm + SM_QH(buf) + doff, g_qh + gidx, true);
            cp16(sm + SM_QL(buf) + doff, g_ql + gidx, true);
        }
        asm volatile("cp.async.commit_group;" ::: "memory");
    };

    auto issueV = [&](int c, int buf) {
        int r0 = c * 32;
#pragma unroll
        for (int j = 0; j < 8; ++j) {
            int id = tid + j * 256;
            int row = id >> 6, cc = id & 63;
            int n = q0 - 127 + r0 + row;
            bool valid = (n >= 0) && (n < NN);
            size_t gidx = ((size_t)(bbase + (valid ? n : 0))) * EE + 2 * DD + cc * 8;
            uint32_t doff = (uint32_t)(row * V_STR + cc * 8) * 2;
            cp16(sm + SM_VH(buf) + doff, g_qh + gidx, valid);
            cp16(sm + SM_VL(buf) + doff, g_ql + gidx, valid);
        }
        asm volatile("cp.async.commit_group;" ::: "memory");
    };

    float accA[6][4];
#pragma unroll
    for (int ni = 0; ni < 6; ++ni)
#pragma unroll
        for (int q = 0; q < 4; ++q) accA[ni][q] = 0.f;

    const int a_row = wr * 16 + (lane & 15);
    const int a_kc  = (lane >> 4) * 8;
    const int bA_row = wc * 48 + ((lane >> 4) << 3) + (lane & 7);
    const int bA_kc  = ((lane >> 3) & 1) * 8;

    issueA(0, 0);
    for (int c = 0; c < 8; ++c) {
        const int buf = c & 1;
        if (c < 7) {
            issueA(c + 1, buf ^ 1);
            asm volatile("cp.async.wait_group 1;" ::: "memory");
        } else {
            asm volatile("cp.async.wait_group 0;" ::: "memory");
        }
        __syncthreads();

#pragma unroll
        for (int ks = 0; ks < 4; ++ks) {
            uint32_t ah[4], al[4];
            LDMX4(ah[0], ah[1], ah[2], ah[3],
                  sm + SM_QH(buf) + (uint32_t)(a_row * QK_STR + a_kc + ks * 16) * 2);
            LDMX4(al[0], al[1], al[2], al[3],
                  sm + SM_QL(buf) + (uint32_t)(a_row * QK_STR + a_kc + ks * 16) * 2);
            uint32_t bh[6][2], bl[6][2];
#pragma unroll
            for (int np = 0; np < 3; ++np) {
                uint32_t off = (uint32_t)((bA_row + np * 16) * QK_STR + bA_kc + ks * 16) * 2;
                uint32_t r0, r1, r2, r3;
                LDMX4(r0, r1, r2, r3, sm + SM_KH(buf) + off);
                bh[2 * np][0] = r0; bh[2 * np][1] = r1;
                bh[2 * np + 1][0] = r2; bh[2 * np + 1][1] = r3;
                LDMX4(r0, r1, r2, r3, sm + SM_KL(buf) + off);
                bl[2 * np][0] = r0; bl[2 * np][1] = r1;
                bl[2 * np + 1][0] = r2; bl[2 * np + 1][1] = r3;
            }
#pragma unroll
            for (int ni = 0; ni < 6; ++ni) {
                MMA16816(accA[ni], ah, bh[ni][0], bh[ni][1]);
                MMA16816(accA[ni], ah, bl[ni][0], bl[ni][1]);
                MMA16816(accA[ni], al, bh[ni][0], bh[ni][1]);
            }
        }
        __syncthreads();
    }

#pragma unroll
    for (int ni = 0; ni < 6; ++ni) {
        int row = wr * 16 + (lane >> 2);
        int col = wc * 48 + ni * 8 + (lane & 3) * 2;
        sS[row * S_STR + col] = accA[ni][0];
        sS[row * S_STR + col + 1] = accA[ni][1];
        sS[(row + 8) * S_STR + col] = accA[ni][2];
        sS[(row + 8) * S_STR + col + 1] = accA[ni][3];
    }

    issueV(0, 0);
    issueV(1, 1);
    __syncthreads();

#pragma unroll
    for (int ii = 0; ii < 4; ++ii) {
        int i = wid * 4 + ii;
        float vals[4];
        float m = -CUDART_INF_F;
#pragma unroll
        for (int t = 0; t < 4; ++t) {
            vals[t] = sS[i * S_STR + i + lane + 32 * t];
            m = fmaxf(m, vals[t]);
        }
#pragma unroll
        for (int o = 16; o > 0; o >>= 1)
            m = fmaxf(m, __shfl_xor_sync(0xffffffffu, m, o));
        float s = 0.f;
#pragma unroll
        for (int t = 0; t < 4; ++t) s += __expf(vals[t] - m);
#pragma unroll
        for (int o = 16; o > 0; o >>= 1)
            s += __shfl_xor_sync(0xffffffffu, s, o);
        float inv = 1.f / s;
#pragma unroll
        for (int t = 0; t < 6; ++t) {
            int r = lane + 32 * t;
            int w = r - i;
            float val = (w >= 0 && w < WW) ? __expf(sS[i * S_STR + r] - m) * inv : 0.f;
            __nv_bfloat16 h = __float2bfloat16_rn(val);
            __nv_bfloat16 l = __float2bfloat16_rn(val - __bfloat162float(h));
            sPh[i * P_STR + r] = h;
            sPl[i * P_STR + r] = l;
        }
    }
    __syncthreads();

    float accO[16][4];
#pragma unroll
    for (int ni = 0; ni < 16; ++ni)
#pragma unroll
        for (int q = 0; q < 4; ++q) accO[ni][q] = 0.f;

    const int pa_row = wr * 16 + (lane & 15);
    const int v_row  = (lane & 15);
    const int v_col0 = wc * 128 + ((lane >> 4) << 3);

    for (int c = 0; c < 6; ++c) {
        if (c < 5) asm volatile("cp.async.wait_group 1;" ::: "memory");
        else       asm volatile("cp.async.wait_group 0;" ::: "memory");
        __syncthreads();
        const int buf = c & 1;

#pragma unroll
        for (int ks = 0; ks < 2; ++ks) {
            int kg = c * 32 + ks * 16;
            uint32_t ph[4], pl[4];
            LDMX4(ph[0], ph[1], ph[2], ph[3],
                  sm + SM_PH + (uint32_t)(pa_row * P_STR + kg + (lane >> 4) * 8) * 2);
            LDMX4(pl[0], pl[1], pl[2], pl[3],
                  sm + SM_PL + (uint32_t)(pa_row * P_STR + kg + (lane >> 4) * 8) * 2);
#pragma unroll
            for (int nt = 0; nt < 8; ++nt) {
                uint32_t off = (uint32_t)((ks * 16 + v_row) * V_STR + v_col0 + nt * 16) * 2;
                uint32_t h0, h1, h2, h3, l0, l1, l2, l3;
                LDMX4T(h0, h1, h2, h3, sm + SM_VH(buf) + off);
                LDMX4T(l0, l1, l2, l3, sm + SM_VL(buf) + off);
                MMA16816(accO[2 * nt], ph, h0, h1);
                MMA16816(accO[2 * nt + 1], ph, h2, h3);
                MMA16816(accO[2 * nt], ph, l0, l1);
                MMA16816(accO[2 * nt + 1], ph, l2, l3);
                MMA16816(accO[2 * nt], pl, h0, h1);
                MMA16816(accO[2 * nt + 1], pl, h2, h3);
            }
        }
        __syncthreads();
        if (c + 2 < 6) issueV(c + 2, buf);
    }

    const int orow = q0 + wr * 16 + (lane >> 2);
    const int ocol = wc * 128 + (lane & 3) * 2;
#pragma unroll
    for (int ni = 0; ni < 16; ++ni) {
        int col = ocol + ni * 8;
        *(float2*)&out[((size_t)(bbase + orow)) * DD + col] =
            make_float2(accO[ni][0], accO[ni][1]);
        *(float2*)&out[((size_t)(bbase + orow + 8)) * DD + col] =
            make_float2(accO[ni][2], accO[ni][3]);
    }
}

extern "C" void kernel_launch(void* const* d_in, const int* in_sizes, int n_in,
                              void* d_out, int out_size) {
    const float* x  = (const float*)d_in[0];
    const float* wl = (const float*)d_in[1];
    float* out = (float*)d_out;

    cudaFuncSetAttribute(qkv_mma_kernel,
                         cudaFuncAttributeMaxDynamicSharedMemorySize, SMEM_QKV);
    cudaFuncSetAttribute(attn_tc_kernel,
                         cudaFuncAttributeMaxDynamicSharedMemorySize, SMEM_ATTN);

    const int nx4 = BB * NN * FF / 4;
    const int nw4 = EE * FF / 4;
    conv_x_kernel<<<(nx4 + 255) / 256, 256>>>(x);
    conv_w_kernel<<<(nw4 + 255) / 256, 256>>>(wl);

    dim3 g1(EE / 128, (BB * NN) / 128);   // 12 x 32
    qkv_mma_kernel<<<g1, 256, SMEM_QKV>>>();

    dim3 g2(NN / 32, BB);                 // 64 x 2
    attn_tc_kernel<<<g2, 256, SMEM_ATTN>>>(out);
}

// round 13
// speedup vs baseline: 2.7871x; 1.1202x over previous
#include <cuda_runtime.h>
#include <cuda_bf16.h>
#include <math_constants.h>
#include <cstdint>

#define BB 2
#define NN 2048
#define FF 512
#define DD 512
#define EE 1536   // 3*DD
#define WW 128

// scratch buffers: qkv as bf16 hi/lo split
__device__ __nv_bfloat16 g_qh[BB * NN * EE];
__device__ __nv_bfloat16 g_ql[BB * NN * EE];
__device__ __nv_bfloat16 g_xhi[BB * NN * FF];
__device__ __nv_bfloat16 g_xlo[BB * NN * FF];
__device__ __nv_bfloat16 g_whi[EE * FF];
__device__ __nv_bfloat16 g_wlo[EE * FF];

__device__ __forceinline__ uint32_t smem_u32(const void* p) {
    uint32_t a;
    asm("{ .reg .u64 t; cvta.to.shared.u64 t, %1; cvt.u32.u64 %0, t; }"
        : "=r"(a) : "l"(p));
    return a;
}

__device__ __forceinline__ void cp16(uint32_t dst, const void* src, bool valid) {
    int sz = valid ? 16 : 0;
    asm volatile("cp.async.cg.shared.global [%0], [%1], 16, %2;"
                 :: "r"(dst), "l"(src), "r"(sz) : "memory");
}

#define LDMX4(r0, r1, r2, r3, addr) \
    asm volatile("ldmatrix.sync.aligned.m8n8.x4.shared.b16 {%0, %1, %2, %3}, [%4];" \
                 : "=r"(r0), "=r"(r1), "=r"(r2), "=r"(r3) : "r"(addr))

#define LDMX4T(r0, r1, r2, r3, addr) \
    asm volatile("ldmatrix.sync.aligned.m8n8.x4.trans.shared.b16 {%0, %1, %2, %3}, [%4];" \
                 : "=r"(r0), "=r"(r1), "=r"(r2), "=r"(r3) : "r"(addr))

#define MMA16816(acc, a, b0, b1) \
    asm volatile("mma.sync.aligned.m16n8k16.row.col.f32.bf16.bf16.f32 " \
                 "{%0, %1, %2, %3}, {%4, %5, %6, %7}, {%8, %9}, {%0, %1, %2, %3};" \
                 : "+f"((acc)[0]), "+f"((acc)[1]), "+f"((acc)[2]), "+f"((acc)[3]) \
                 : "r"((a)[0]), "r"((a)[1]), "r"((a)[2]), "r"((a)[3]), \
                   "r"(b0), "r"(b1))

// ---------------------------------------------------------------------------
// Conversion: fp32 -> (bf16 hi, bf16 lo), X and W in one kernel
// ---------------------------------------------------------------------------
__device__ __forceinline__ void split4(const float* __restrict__ src, int i,
                                       __nv_bfloat16* __restrict__ hi,
                                       __nv_bfloat16* __restrict__ lo) {
    float4 v = ((const float4*)src)[i];
    __nv_bfloat16 h0 = __float2bfloat16_rn(v.x);
    __nv_bfloat16 h1 = __float2bfloat16_rn(v.y);
    __nv_bfloat16 h2 = __float2bfloat16_rn(v.z);
    __nv_bfloat16 h3 = __float2bfloat16_rn(v.w);
    __nv_bfloat16 l0 = __float2bfloat16_rn(v.x - __bfloat162float(h0));
    __nv_bfloat16 l1 = __float2bfloat16_rn(v.y - __bfloat162float(h1));
    __nv_bfloat16 l2 = __float2bfloat16_rn(v.z - __bfloat162float(h2));
    __nv_bfloat16 l3 = __float2bfloat16_rn(v.w - __bfloat162float(h3));
    __nv_bfloat162* hp = (__nv_bfloat162*)hi;
    __nv_bfloat162* lp = (__nv_bfloat162*)lo;
    hp[2 * i]     = __nv_bfloat162{h0, h1};
    hp[2 * i + 1] = __nv_bfloat162{h2, h3};
    lp[2 * i]     = __nv_bfloat162{l0, l1};
    lp[2 * i + 1] = __nv_bfloat162{l2, l3};
}

#define NX4 (BB * NN * FF / 4)
#define NW4 (EE * FF / 4)

__global__ void conv_all_kernel(const float* __restrict__ x,
                                const float* __restrict__ wl) {
    int i = blockIdx.x * blockDim.x + threadIdx.x;
    if (i < NX4) split4(x, i, g_xhi, g_xlo);
    else if (i < NX4 + NW4) split4(wl, i - NX4, g_whi, g_wlo);
}

// ---------------------------------------------------------------------------
// Kernel 1: QKV GEMM, fused split-bf16 (Xhi.Whi + Xhi.Wlo + Xlo.Whi).
// CTA tile 128x128, 8 warps (4Mx2N), warp tile 32x64, BK=32.
// 3-stage cp.async ring, ONE __syncthreads per k-iter.
// smem layout: 64B rows with chunk swizzle c^((row>>1)&3)  -> conflict-free
// ldmatrix and 32KB per stage (4 arrays x 8KB); 3 stages = 96KB.
// ---------------------------------------------------------------------------
#define BK 32
#define QSTG 32768                     // bytes per stage (4 arrays x 8KB)
#define SM_AH(buf) ((buf) * QSTG + 0)
#define SM_AL(buf) ((buf) * QSTG + 8192)
#define SM_BH(buf) ((buf) * QSTG + 16384)
#define SM_BL(buf) ((buf) * QSTG + 24576)
#define SMEM_QKV (3 * QSTG)            // 98304

__device__ __forceinline__ uint32_t swz(int row, int chunk) {
    return (uint32_t)(row * 64 + ((chunk ^ ((row >> 1) & 3)) << 4));
}

extern __shared__ char dynsm[];

__global__ __launch_bounds__(256, 2)
void qkv_mma_kernel() {
    const int tid = threadIdx.x;
    const int lane = tid & 31;
    const int wid = tid >> 5;
    const int wr = wid & 3;
    const int wc = wid >> 2;
    const int bn = blockIdx.x * 128;
    const int bm = blockIdx.y * 128;

    const uint32_t sm = smem_u32(dynsm);

    float acc[2][8][4];
#pragma unroll
    for (int mi = 0; mi < 2; ++mi)
#pragma unroll
        for (int ni = 0; ni < 8; ++ni)
#pragma unroll
            for (int q = 0; q < 4; ++q) acc[mi][ni][q] = 0.f;

    // loads: 2048 chunks of 16B per stage (4 arrays x 128 rows x 4 chunks)
    auto issue_loads = [&](int t, int buf) {
        int k0 = t * BK;
#pragma unroll
        for (int j = 0; j < 8; ++j) {
            int id = tid + j * 256;          // 0..2047
            int arr = id >> 9;               // 0..3
            int cid = id & 511;
            int row = cid >> 2;
            int c   = cid & 3;
            uint32_t doff = swz(row, c);
            const __nv_bfloat16* gp;
            uint32_t base;
            if (arr == 0)      { gp = g_xhi + (size_t)(bm + row) * FF + k0 + c * 8; base = SM_AH(buf); }
            else if (arr == 1) { gp = g_xlo + (size_t)(bm + row) * FF + k0 + c * 8; base = SM_AL(buf); }
            else if (arr == 2) { gp = g_whi + (size_t)(bn + row) * FF + k0 + c * 8; base = SM_BH(buf); }
            else               { gp = g_wlo + (size_t)(bn + row) * FF + k0 + c * 8; base = SM_BL(buf); }
            cp16(sm + base + doff, gp, true);
        }
        asm volatile("cp.async.commit_group;" ::: "memory");
    };

    issue_loads(0, 0);
    issue_loads(1, 1);

    const int a_row = wr * 32 + (lane & 15);
    const int a_ch  = (lane >> 4);           // + ks*2
    const int b_row = wc * 64 + ((lane >> 4) << 3) + (lane & 7);
    const int b_ch  = ((lane >> 3) & 1);     // + ks*2

    for (int t = 0; t < 16; ++t) {
        const int buf = t % 3;
        if (t < 14) {
            asm volatile("cp.async.wait_group 1;" ::: "memory");
        } else {
            asm volatile("cp.async.wait_group 0;" ::: "memory");
        }
        __syncthreads();
        if (t + 2 < 16) issue_loads(t + 2, (t + 2) % 3);

#pragma unroll
        for (int ks = 0; ks < 2; ++ks) {
            uint32_t ah[2][4], al[2][4];
#pragma unroll
            for (int mi = 0; mi < 2; ++mi) {
                int row = a_row + mi * 16;
                uint32_t off = swz(row, a_ch + ks * 2);
                LDMX4(ah[mi][0], ah[mi][1], ah[mi][2], ah[mi][3], sm + SM_AH(buf) + off);
                LDMX4(al[mi][0], al[mi][1], al[mi][2], al[mi][3], sm + SM_AL(buf) + off);
            }
#pragma unroll
            for (int np = 0; np < 4; ++np) {
                int row = b_row + np * 16;
                uint32_t off = swz(row, b_ch + ks * 2);
                uint32_t h0, h1, h2, h3, l0, l1, l2, l3;
                LDMX4(h0, h1, h2, h3, sm + SM_BH(buf) + off);
                LDMX4(l0, l1, l2, l3, sm + SM_BL(buf) + off);
#pragma unroll
                for (int mi = 0; mi < 2; ++mi) {
                    MMA16816(acc[mi][2 * np],     ah[mi], h0, h1);
                    MMA16816(acc[mi][2 * np + 1], ah[mi], h2, h3);
                    MMA16816(acc[mi][2 * np],     ah[mi], l0, l1);
                    MMA16816(acc[mi][2 * np + 1], ah[mi], l2, l3);
                    MMA16816(acc[mi][2 * np],     al[mi], h0, h1);
                    MMA16816(acc[mi][2 * np + 1], al[mi], h2, h3);
                }
            }
        }
    }
    __syncthreads();   // all warps done with ring buffers before smem reuse

    // ---- epilogue: stage hi/lo bf16 in smem, then coalesced 16B stores ----
    __nv_bfloat16* const sOutH = (__nv_bfloat16*)dynsm;            // 32KB
    __nv_bfloat16* const sOutL = (__nv_bfloat16*)(dynsm + 32768);  // 32KB

    const int em = wr * 32 + (lane >> 2);
    const int en = wc * 64 + (lane & 3) * 2;
#pragma unroll
    for (int mi = 0; mi < 2; ++mi) {
#pragma unroll
        for (int ni = 0; ni < 8; ++ni) {
#pragma unroll
            for (int half = 0; half < 2; ++half) {
                int row = em + mi * 16 + half * 8;
                int col = en + ni * 8;
                float v0 = acc[mi][ni][2 * half], v1 = acc[mi][ni][2 * half + 1];
                __nv_bfloat16 h0 = __float2bfloat16_rn(v0);
                __nv_bfloat16 h1 = __float2bfloat16_rn(v1);
                __nv_bfloat16 l0 = __float2bfloat16_rn(v0 - __bfloat162float(h0));
                __nv_bfloat16 l1 = __float2bfloat16_rn(v1 - __bfloat162float(h1));
                *(__nv_bfloat162*)&sOutH[row * 128 + col] = __nv_bfloat162{h0, h1};
                *(__nv_bfloat162*)&sOutL[row * 128 + col] = __nv_bfloat162{l0, l1};
            }
        }
    }
    __syncthreads();

#pragma unroll
    for (int j = 0; j < 8; ++j) {
        int id = tid + j * 256;          // 0..2047
        int row = id >> 4;
        int c16 = id & 15;
        uint4 v = *(uint4*)&sOutH[row * 128 + c16 * 8];
        *(uint4*)&g_qh[(size_t)(bm + row) * EE + bn + c16 * 8] = v;
    }
#pragma unroll
    for (int j = 0; j < 8; ++j) {
        int id = tid + j * 256;
        int row = id >> 4;
        int c16 = id & 15;
        uint4 v = *(uint4*)&sOutL[row * 128 + c16 * 8];
        *(uint4*)&g_ql[(size_t)(bm + row) * EE + bn + c16 * 8] = v;
    }
}

// ---------------------------------------------------------------------------
// Kernel 2: sliding-window attention via mma.sync bf16 (unchanged from R10/12).
// ---------------------------------------------------------------------------
#define SM_QH(buf)  ((buf) * 64512 + 0)
#define SM_QL(buf)  ((buf) * 64512 + 4608)
#define SM_KH(buf)  ((buf) * 64512 + 9216)
#define SM_KL(buf)  ((buf) * 64512 + 36864)
#define SM_VH(buf)  ((buf) * 66560 + 0)
#define SM_VL(buf)  ((buf) * 66560 + 33280)
#define SM_S        133120
#define SM_PH       158208
#define SM_PL       171008
#define SMEM_ATTN   183808
#define QK_STR 72
#define V_STR  520
#define P_STR  200
#define S_STR  196

__global__ __launch_bounds__(256, 1)
void attn_tc_kernel(float* __restrict__ out) {
    const int tid = threadIdx.x;
    const int lane = tid & 31;
    const int wid = tid >> 5;
    const int wr = wid & 1;
    const int wc = wid >> 1;
    const int b  = blockIdx.y;
    const int q0 = blockIdx.x * 32;
    const int bbase = b * NN;

    const uint32_t sm = smem_u32(dynsm);
    float* const sS = (float*)(dynsm + SM_S);
    __nv_bfloat16* const sPh = (__nv_bfloat16*)(dynsm + SM_PH);
    __nv_bfloat16* const sPl = (__nv_bfloat16*)(dynsm + SM_PL);

    auto issueA = [&](int c, int buf) {
        int k0 = c * 64;
#pragma unroll
        for (int j = 0; j < 6; ++j) {
            int id = tid + j * 256;
            int row = id >> 3, cc = id & 7;
            int n = q0 - 127 + row;
            bool valid = (row < 160) && (n >= 0) && (n < NN);
            size_t gidx = ((size_t)(bbase + (valid ? n : 0))) * EE + DD + k0 + cc * 8;
            uint32_t doff = (uint32_t)(row * QK_STR + cc * 8) * 2;
            cp16(sm + SM_KH(buf) + doff, g_qh + gidx, valid);
            cp16(sm + SM_KL(buf) + doff, g_ql + gidx, valid);
        }
        {
            int row = tid >> 3, cc = tid & 7;
            size_t gidx = ((size_t)(bbase + q0 + row)) * EE + k0 + cc * 8;
            uint32_t doff = (uint32_t)(row * QK_STR + cc * 8) * 2;
            cp16(sm + SM_QH(buf) + doff, g_qh + gidx, true);
            cp16(sm + SM_QL(buf) + doff, g_ql + gidx, true);
        }
        asm volatile("cp.async.commit_group;" ::: "memory");
    };

    auto issueV = [&](int c, int buf) {
        int r0 = c * 32;
#pragma unroll
        for (int j = 0; j < 8; ++j) {
            int id = tid + j * 256;
            int row = id >> 6, cc = id & 63;
            int n = q0 - 127 + r0 + row;
            bool valid = (n >= 0) && (n < NN);
            size_t gidx = ((size_t)(bbase + (valid ? n : 0))) * EE + 2 * DD + cc * 8;
            uint32_t doff = (uint32_t)(row * V_STR + cc * 8) * 2;
            cp16(sm + SM_VH(buf) + doff, g_qh + gidx, valid);
            cp16(sm + SM_VL(buf) + doff, g_ql + gidx, valid);
        }
        asm volatile("cp.async.commit_group;" ::: "memory");
    };

    float accA[6][4];
#pragma unroll
    for (int ni = 0; ni < 6; ++ni)
#pragma unroll
        for (int q = 0; q < 4; ++q) accA[ni][q] = 0.f;

    const int a_row = wr * 16 + (lane & 15);
    const int a_kc  = (lane >> 4) * 8;
    const int bA_row = wc * 48 + ((lane >> 4) << 3) + (lane & 7);
    const int bA_kc  = ((lane >> 3) & 1) * 8;

    issueA(0, 0);
    for (int c = 0; c < 8; ++c) {
        const int buf = c & 1;
        if (c < 7) {
            issueA(c + 1, buf ^ 1);
            asm volatile("cp.async.wait_group 1;" ::: "memory");
        } else {
            asm volatile("cp.async.wait_group 0;" ::: "memory");
        }
        __syncthreads();

#pragma unroll
        for (int ks = 0; ks < 4; ++ks) {
            uint32_t ah[4], al[4];
            LDMX4(ah[0], ah[1], ah[2], ah[3],
                  sm + SM_QH(buf) + (uint32_t)(a_row * QK_STR + a_kc + ks * 16) * 2);
            LDMX4(al[0], al[1], al[2], al[3],
                  sm + SM_QL(buf) + (uint32_t)(a_row * QK_STR + a_kc + ks * 16) * 2);
            uint32_t bh[6][2], bl[6][2];
#pragma unroll
            for (int np = 0; np < 3; ++np) {
                uint32_t off = (uint32_t)((bA_row + np * 16) * QK_STR + bA_kc + ks * 16) * 2;
                uint32_t r0, r1, r2, r3;
                LDMX4(r0, r1, r2, r3, sm + SM_KH(buf) + off);
                bh[2 * np][0] = r0; bh[2 * np][1] = r1;
                bh[2 * np + 1][0] = r2; bh[2 * np + 1][1] = r3;
                LDMX4(r0, r1, r2, r3, sm + SM_KL(buf) + off);
                bl[2 * np][0] = r0; bl[2 * np][1] = r1;
                bl[2 * np + 1][0] = r2; bl[2 * np + 1][1] = r3;
            }
#pragma unroll
            for (int ni = 0; ni < 6; ++ni) {
                MMA16816(accA[ni], ah, bh[ni][0], bh[ni][1]);
                MMA16816(accA[ni], ah, bl[ni][0], bl[ni][1]);
                MMA16816(accA[ni], al, bh[ni][0], bh[ni][1]);
            }
        }
        __syncthreads();
    }

#pragma unroll
    for (int ni = 0; ni < 6; ++ni) {
        int row = wr * 16 + (lane >> 2);
        int col = wc * 48 + ni * 8 + (lane & 3) * 2;
        sS[row * S_STR + col] = accA[ni][0];
        sS[row * S_STR + col + 1] = accA[ni][1];
        sS[(row + 8) * S_STR + col] = accA[ni][2];
        sS[(row + 8) * S_STR + col + 1] = accA[ni][3];
    }

    issueV(0, 0);
    issueV(1, 1);
    __syncthreads();

#pragma unroll
    for (int ii = 0; ii < 4; ++ii) {
        int i = wid * 4 + ii;
        float vals[4];
        float m = -CUDART_INF_F;
#pragma unroll
        for (int t = 0; t < 4; ++t) {
            vals[t] = sS[i * S_STR + i + lane + 32 * t];
            m = fmaxf(m, vals[t]);
        }
#pragma unroll
        for (int o = 16; o > 0; o >>= 1)
            m = fmaxf(m, __shfl_xor_sync(0xffffffffu, m, o));
        float s = 0.f;
#pragma unroll
        for (int t = 0; t < 4; ++t) s += __expf(vals[t] - m);
#pragma unroll
        for (int o = 16; o > 0; o >>= 1)
            s += __shfl_xor_sync(0xffffffffu, s, o);
        float inv = 1.f / s;
#pragma unroll
        for (int t = 0; t < 6; ++t) {
            int r = lane + 32 * t;
            int w = r - i;
            float val = (w >= 0 && w < WW) ? __expf(sS[i * S_STR + r] - m) * inv : 0.f;
            __nv_bfloat16 h = __float2bfloat16_rn(val);
            __nv_bfloat16 l = __float2bfloat16_rn(val - __bfloat162float(h));
            sPh[i * P_STR + r] = h;
            sPl[i * P_STR + r] = l;
        }
    }
    __syncthreads();

    float accO[16][4];
#pragma unroll
    for (int ni = 0; ni < 16; ++ni)
#pragma unroll
        for (int q = 0; q < 4; ++q) accO[ni][q] = 0.f;

    const int pa_row = wr * 16 + (lane & 15);
    const int v_row  = (lane & 15);
    const int v_col0 = wc * 128 + ((lane >> 4) << 3);

    for (int c = 0; c < 6; ++c) {
        if (c < 5) asm volatile("cp.async.wait_group 1;" ::: "memory");
        else       asm volatile("cp.async.wait_group 0;" ::: "memory");
        __syncthreads();
        const int buf = c & 1;

#pragma unroll
        for (int ks = 0; ks < 2; ++ks) {
            int kg = c * 32 + ks * 16;
            uint32_t ph[4], pl[4];
            LDMX4(ph[0], ph[1], ph[2], ph[3],
                  sm + SM_PH + (uint32_t)(pa_row * P_STR + kg + (lane >> 4) * 8) * 2);
            LDMX4(pl[0], pl[1], pl[2], pl[3],
                  sm + SM_PL + (uint32_t)(pa_row * P_STR + kg + (lane >> 4) * 8) * 2);
#pragma unroll
            for (int nt = 0; nt < 8; ++nt) {
                uint32_t off = (uint32_t)((ks * 16 + v_row) * V_STR + v_col0 + nt * 16) * 2;
                uint32_t h0, h1, h2, h3, l0, l1, l2, l3;
                LDMX4T(h0, h1, h2, h3, sm + SM_VH(buf) + off);
                LDMX4T(l0, l1, l2, l3, sm + SM_VL(buf) + off);
                MMA16816(accO[2 * nt], ph, h0, h1);
                MMA16816(accO[2 * nt + 1], ph, h2, h3);
                MMA16816(accO[2 * nt], ph, l0, l1);
                MMA16816(accO[2 * nt + 1], ph, l2, l3);
                MMA16816(accO[2 * nt], pl, h0, h1);
                MMA16816(accO[2 * nt + 1], pl, h2, h3);
            }
        }
        __syncthreads();
        if (c + 2 < 6) issueV(c + 2, buf);
    }

    const int orow = q0 + wr * 16 + (lane >> 2);
    const int ocol = wc * 128 + (lane & 3) * 2;
#pragma unroll
    for (int ni = 0; ni < 16; ++ni) {
        int col = ocol + ni * 8;
        *(float2*)&out[((size_t)(bbase + orow)) * DD + col] =
            make_float2(accO[ni][0], accO[ni][1]);
        *(float2*)&out[((size_t)(bbase + orow + 8)) * DD + col] =
            make_float2(accO[ni][2], accO[ni][3]);
    }
}

extern "C" void kernel_launch(void* const* d_in, const int* in_sizes, int n_in,
                              void* d_out, int out_size) {
    const float* x  = (const float*)d_in[0];
    const float* wl = (const float*)d_in[1];
    float* out = (float*)d_out;

    cudaFuncSetAttribute(qkv_mma_kernel,
                         cudaFuncAttributeMaxDynamicSharedMemorySize, SMEM_QKV);
    cudaFuncSetAttribute(attn_tc_kernel,
                         cudaFuncAttributeMaxDynamicSharedMemorySize, SMEM_ATTN);

    const int ntot = NX4 + NW4;
    conv_all_kernel<<<(ntot + 255) / 256, 256>>>(x, wl);

    dim3 g1(EE / 128, (BB * NN) / 128);   // 12 x 32
    qkv_mma_kernel<<<g1, 256, SMEM_QKV>>>();

    dim3 g2(NN / 32, BB);                 // 64 x 2
    attn_tc_kernel<<<g2, 256, SMEM_ATTN>>>(out);
}

// round 14
// speedup vs baseline: 3.2990x; 1.1836x over previous
#include <cuda_runtime.h>
#include <cuda_fp16.h>
#include <math_constants.h>
#include <cstdint>

#define BB 2
#define NN 2048
#define FF 512
#define DD 512
#define EE 1536   // 3*DD
#define WW 128

// scratch: fp16 "hi" and "combined" (h + 64*lo) arrays
__device__ __half g_qh[BB * NN * EE];
__device__ __half g_qc[BB * NN * EE];
__device__ __half g_xh[BB * NN * FF];
__device__ __half g_xc[BB * NN * FF];
__device__ __half g_wh[EE * FF];
__device__ __half g_wc[EE * FF];

#define SPLIT_S 64.0f
#define INV_S   0.015625f

__device__ __forceinline__ uint32_t smem_u32(const void* p) {
    uint32_t a;
    asm("{ .reg .u64 t; cvta.to.shared.u64 t, %1; cvt.u32.u64 %0, t; }"
        : "=r"(a) : "l"(p));
    return a;
}

__device__ __forceinline__ void cp16(uint32_t dst, const void* src, bool valid) {
    int sz = valid ? 16 : 0;
    asm volatile("cp.async.cg.shared.global [%0], [%1], 16, %2;"
                 :: "r"(dst), "l"(src), "r"(sz) : "memory");
}

#define LDMX4(r0, r1, r2, r3, addr) \
    asm volatile("ldmatrix.sync.aligned.m8n8.x4.shared.b16 {%0, %1, %2, %3}, [%4];" \
                 : "=r"(r0), "=r"(r1), "=r"(r2), "=r"(r3) : "r"(addr))

#define LDMX4T(r0, r1, r2, r3, addr) \
    asm volatile("ldmatrix.sync.aligned.m8n8.x4.trans.shared.b16 {%0, %1, %2, %3}, [%4];" \
                 : "=r"(r0), "=r"(r1), "=r"(r2), "=r"(r3) : "r"(addr))

#define MMA16816(acc, a, b0, b1) \
    asm volatile("mma.sync.aligned.m16n8k16.row.col.f32.f16.f16.f32 " \
                 "{%0, %1, %2, %3}, {%4, %5, %6, %7}, {%8, %9}, {%0, %1, %2, %3};" \
                 : "+f"((acc)[0]), "+f"((acc)[1]), "+f"((acc)[2]), "+f"((acc)[3]) \
                 : "r"((a)[0]), "r"((a)[1]), "r"((a)[2]), "r"((a)[3]), \
                   "r"(b0), "r"(b1))

// ---------------------------------------------------------------------------
// Conversion: fp32 -> (fp16 h, fp16 c = h + 64*(x - h))
// ---------------------------------------------------------------------------
__device__ __forceinline__ void split4(const float* __restrict__ src, int i,
                                       __half* __restrict__ hp_,
                                       __half* __restrict__ cp_) {
    float4 v = ((const float4*)src)[i];
    float f[4] = {v.x, v.y, v.z, v.w};
    __half h[4], c[4];
#pragma unroll
    for (int j = 0; j < 4; ++j) {
        h[j] = __float2half_rn(f[j]);
        float hl = __half2float(h[j]);
        c[j] = __float2half_rn(fmaf(SPLIT_S, f[j] - hl, hl));
    }
    __half2* hp = (__half2*)hp_;
    __half2* cp = (__half2*)cp_;
    hp[2 * i]     = __halves2half2(h[0], h[1]);
    hp[2 * i + 1] = __halves2half2(h[2], h[3]);
    cp[2 * i]     = __halves2half2(c[0], c[1]);
    cp[2 * i + 1] = __halves2half2(c[2], c[3]);
}

#define NX4 (BB * NN * FF / 4)
#define NW4 (EE * FF / 4)

__global__ void conv_all_kernel(const float* __restrict__ x,
                                const float* __restrict__ wl) {
    int i = blockIdx.x * blockDim.x + threadIdx.x;
    if (i < NX4) split4(x, i, g_xh, g_xc);
    else if (i < NX4 + NW4) split4(wl, i - NX4, g_wh, g_wc);
}

// ---------------------------------------------------------------------------
// Kernel 1: QKV GEMM, fp16 Karatsuba 2-pass: C = (63*Xh.Wh + Xc.Wc)/64.
// CTA tile 128x128, 8 warps (4Mx2N), warp tile 32x64, BK=64.
// Pass 1 (t=0..7): Xh.Wh; acc *= 63; pass 2 (t=8..15): += Xc.Wc; out /= 64.
// 3-stage cp.async ring, one __syncthreads per iter.
// smem: 128B rows, chunk swizzle c^(row&7); 32KB/stage, 96KB total, 2 CTA/SM.
// ---------------------------------------------------------------------------
#define BK 64
#define QSTG 32768
#define SM_A(buf) ((buf) * QSTG + 0)
#define SM_B(buf) ((buf) * QSTG + 16384)
#define SMEM_QKV (3 * QSTG)            // 98304

__device__ __forceinline__ uint32_t swz128(int row, int ch) {
    return (uint32_t)(row * 128 + ((ch ^ (row & 7)) << 4));
}

extern __shared__ char dynsm[];

__global__ __launch_bounds__(256, 2)
void qkv_mma_kernel() {
    const int tid = threadIdx.x;
    const int lane = tid & 31;
    const int wid = tid >> 5;
    const int wr = wid & 3;
    const int wc = wid >> 2;
    const int bn = blockIdx.x * 128;
    const int bm = blockIdx.y * 128;

    const uint32_t sm = smem_u32(dynsm);

    float acc[2][8][4];
#pragma unroll
    for (int mi = 0; mi < 2; ++mi)
#pragma unroll
        for (int ni = 0; ni < 8; ++ni)
#pragma unroll
            for (int q = 0; q < 4; ++q) acc[mi][ni][q] = 0.f;

    // 2048 chunks/stage: A 128x64 fp16 (1024) + B 128x64 (1024); 8 per thread
    auto issue_loads = [&](int t, int buf) {
        int pass = t >> 3;
        int k0 = (t & 7) * BK;
        const __half* A = (pass ? g_xc : g_xh) + (size_t)bm * FF + k0;
        const __half* B = (pass ? g_wc : g_wh) + (size_t)bn * FF + k0;
#pragma unroll
        for (int j = 0; j < 8; ++j) {
            int id = tid + j * 256;          // 0..2047
            int arr = id >> 10;
            int cid = id & 1023;
            int row = cid >> 3;
            int c   = cid & 7;
            uint32_t doff = swz128(row, c);
            if (arr == 0) cp16(sm + SM_A(buf) + doff, A + row * FF + c * 8, true);
            else          cp16(sm + SM_B(buf) + doff, B + row * FF + c * 8, true);
        }
        asm volatile("cp.async.commit_group;" ::: "memory");
    };

    issue_loads(0, 0);
    issue_loads(1, 1);

    const int a_row = wr * 32 + (lane & 15);
    const int a_ch  = (lane >> 4);           // + kk*2
    const int b_row = wc * 64 + ((lane >> 4) << 3) + (lane & 7);
    const int b_ch  = ((lane >> 3) & 1);     // + kk*2

    for (int t = 0; t < 16; ++t) {
        const int buf = t % 3;
        if (t < 14) {
            asm volatile("cp.async.wait_group 1;" ::: "memory");
        } else {
            asm volatile("cp.async.wait_group 0;" ::: "memory");
        }
        __syncthreads();
        if (t + 2 < 16) issue_loads(t + 2, (t + 2) % 3);

#pragma unroll
        for (int kk = 0; kk < 4; ++kk) {
            uint32_t af[2][4];
#pragma unroll
            for (int mi = 0; mi < 2; ++mi) {
                int row = a_row + mi * 16;
                LDMX4(af[mi][0], af[mi][1], af[mi][2], af[mi][3],
                      sm + SM_A(buf) + swz128(row, a_ch + kk * 2));
            }
#pragma unroll
            for (int np = 0; np < 4; ++np) {
                int row = b_row + np * 16;
                uint32_t h0, h1, h2, h3;
                LDMX4(h0, h1, h2, h3, sm + SM_B(buf) + swz128(row, b_ch + kk * 2));
#pragma unroll
                for (int mi = 0; mi < 2; ++mi) {
                    MMA16816(acc[mi][2 * np],     af[mi], h0, h1);
                    MMA16816(acc[mi][2 * np + 1], af[mi], h2, h3);
                }
            }
        }
        if (t == 7) {   // pass boundary: acc = 63*M1, then pass 2 adds M2
#pragma unroll
            for (int mi = 0; mi < 2; ++mi)
#pragma unroll
                for (int ni = 0; ni < 8; ++ni)
#pragma unroll
                    for (int q = 0; q < 4; ++q) acc[mi][ni][q] *= 63.0f;
        }
    }
    __syncthreads();

    // epilogue: c = acc/64 -> fp16 h/c split, staged in smem, 16B stores
    __half* const sOutH = (__half*)dynsm;            // 32KB
    __half* const sOutC = (__half*)(dynsm + 32768);  // 32KB

    const int em = wr * 32 + (lane >> 2);
    const int en = wc * 64 + (lane & 3) * 2;
#pragma unroll
    for (int mi = 0; mi < 2; ++mi) {
#pragma unroll
        for (int ni = 0; ni < 8; ++ni) {
#pragma unroll
            for (int half_ = 0; half_ < 2; ++half_) {
                int row = em + mi * 16 + half_ * 8;
                int col = en + ni * 8;
                float v0 = acc[mi][ni][2 * half_] * INV_S;
                float v1 = acc[mi][ni][2 * half_ + 1] * INV_S;
                __half h0 = __float2half_rn(v0);
                __half h1 = __float2half_rn(v1);
                float f0 = __half2float(h0), f1 = __half2float(h1);
                __half c0 = __float2half_rn(fmaf(SPLIT_S, v0 - f0, f0));
                __half c1 = __float2half_rn(fmaf(SPLIT_S, v1 - f1, f1));
                *(__half2*)&sOutH[row * 128 + col] = __halves2half2(h0, h1);
                *(__half2*)&sOutC[row * 128 + col] = __halves2half2(c0, c1);
            }
        }
    }
    __syncthreads();

#pragma unroll
    for (int j = 0; j < 8; ++j) {
        int id = tid + j * 256;
        int row = id >> 4;
        int c16 = id & 15;
        uint4 v = *(uint4*)&sOutH[row * 128 + c16 * 8];
        *(uint4*)&g_qh[(size_t)(bm + row) * EE + bn + c16 * 8] = v;
    }
#pragma unroll
    for (int j = 0; j < 8; ++j) {
        int id = tid + j * 256;
        int row = id >> 4;
        int c16 = id & 15;
        uint4 v = *(uint4*)&sOutC[row * 128 + c16 * 8];
        *(uint4*)&g_qc[(size_t)(bm + row) * EE + bn + c16 * 8] = v;
    }
}

// ---------------------------------------------------------------------------
// Kernel 2: sliding-window attention, fp16 Karatsuba 2-MMA everywhere.
// Phase A: S = (63*Qh.Kh^T + Qc.Kc^T)/64 (dual accumulators).
// Softmax; P split into ph / pc = ph + 64*(p-ph).
// Phase B: out = (63*Ph.Vh + Pc.Vc)/64 (dual accumulators).
// ---------------------------------------------------------------------------
#define SM_QHb(buf)  ((buf) * 64512 + 0)
#define SM_QCb(buf)  ((buf) * 64512 + 4608)
#define SM_KHb(buf)  ((buf) * 64512 + 9216)
#define SM_KCb(buf)  ((buf) * 64512 + 36864)
#define SM_VHb(buf)  ((buf) * 66560 + 0)
#define SM_VCb(buf)  ((buf) * 66560 + 33280)
#define SM_S        133120
#define SM_PH       158208
#define SM_PC       171008
#define SMEM_ATTN   183808
#define QK_STR 72
#define V_STR  520
#define P_STR  200
#define S_STR  196

__global__ __launch_bounds__(256, 1)
void attn_tc_kernel(float* __restrict__ out) {
    const int tid = threadIdx.x;
    const int lane = tid & 31;
    const int wid = tid >> 5;
    const int wr = wid & 1;
    const int wc = wid >> 1;
    const int b  = blockIdx.y;
    const int q0 = blockIdx.x * 32;
    const int bbase = b * NN;

    const uint32_t sm = smem_u32(dynsm);
    float* const sS = (float*)(dynsm + SM_S);
    __half* const sPh = (__half*)(dynsm + SM_PH);
    __half* const sPc = (__half*)(dynsm + SM_PC);

    auto issueA = [&](int c, int buf) {
        int k0 = c * 64;
#pragma unroll
        for (int j = 0; j < 6; ++j) {
            int id = tid + j * 256;
            int row = id >> 3, cc = id & 7;
            int n = q0 - 127 + row;
            bool valid = (row < 160) && (n >= 0) && (n < NN);
            size_t gidx = ((size_t)(bbase + (valid ? n : 0))) * EE + DD + k0 + cc * 8;
            uint32_t doff = (uint32_t)(row * QK_STR + cc * 8) * 2;
            cp16(sm + SM_KHb(buf) + doff, g_qh + gidx, valid);
            cp16(sm + SM_KCb(buf) + doff, g_qc + gidx, valid);
        }
        {
            int row = tid >> 3, cc = tid & 7;
            size_t gidx = ((size_t)(bbase + q0 + row)) * EE + k0 + cc * 8;
            uint32_t doff = (uint32_t)(row * QK_STR + cc * 8) * 2;
            cp16(sm + SM_QHb(buf) + doff, g_qh + gidx, true);
            cp16(sm + SM_QCb(buf) + doff, g_qc + gidx, true);
        }
        asm volatile("cp.async.commit_group;" ::: "memory");
    };

    auto issueV = [&](int c, int buf) {
        int r0 = c * 32;
#pragma unroll
        for (int j = 0; j < 8; ++j) {
            int id = tid + j * 256;
            int row = id >> 6, cc = id & 63;
            int n = q0 - 127 + r0 + row;
            bool valid = (n >= 0) && (n < NN);
            size_t gidx = ((size_t)(bbase + (valid ? n : 0))) * EE + 2 * DD + cc * 8;
            uint32_t doff = (uint32_t)(row * V_STR + cc * 8) * 2;
            cp16(sm + SM_VHb(buf) + doff, g_qh + gidx, valid);
            cp16(sm + SM_VCb(buf) + doff, g_qc + gidx, valid);
        }
        asm volatile("cp.async.commit_group;" ::: "memory");
    };

    float a1[6][4], a2[6][4];
#pragma unroll
    for (int ni = 0; ni < 6; ++ni)
#pragma unroll
        for (int q = 0; q < 4; ++q) { a1[ni][q] = 0.f; a2[ni][q] = 0.f; }

    const int a_row = wr * 16 + (lane & 15);
    const int a_kc  = (lane >> 4) * 8;
    const int bA_row = wc * 48 + ((lane >> 4) << 3) + (lane & 7);
    const int bA_kc  = ((lane >> 3) & 1) * 8;

    issueA(0, 0);
    for (int c = 0; c < 8; ++c) {
        const int buf = c & 1;
        if (c < 7) {
            issueA(c + 1, buf ^ 1);
            asm volatile("cp.async.wait_group 1;" ::: "memory");
        } else {
            asm volatile("cp.async.wait_group 0;" ::: "memory");
        }
        __syncthreads();

#pragma unroll
        for (int ks = 0; ks < 4; ++ks) {
            uint32_t ah[4], ac[4];
            LDMX4(ah[0], ah[1], ah[2], ah[3],
                  sm + SM_QHb(buf) + (uint32_t)(a_row * QK_STR + a_kc + ks * 16) * 2);
            LDMX4(ac[0], ac[1], ac[2], ac[3],
                  sm + SM_QCb(buf) + (uint32_t)(a_row * QK_STR + a_kc + ks * 16) * 2);
            uint32_t kh[6][2], kc[6][2];
#pragma unroll
            for (int np = 0; np < 3; ++np) {
                uint32_t off = (uint32_t)((bA_row + np * 16) * QK_STR + bA_kc + ks * 16) * 2;
                uint32_t r0, r1, r2, r3;
                LDMX4(r0, r1, r2, r3, sm + SM_KHb(buf) + off);
                kh[2 * np][0] = r0; kh[2 * np][1] = r1;
                kh[2 * np + 1][0] = r2; kh[2 * np + 1][1] = r3;
                LDMX4(r0, r1, r2, r3, sm + SM_KCb(buf) + off);
                kc[2 * np][0] = r0; kc[2 * np][1] = r1;
                kc[2 * np + 1][0] = r2; kc[2 * np + 1][1] = r3;
            }
#pragma unroll
            for (int ni = 0; ni < 6; ++ni) {
                MMA16816(a1[ni], ah, kh[ni][0], kh[ni][1]);
                MMA16816(a2[ni], ac, kc[ni][0], kc[ni][1]);
            }
        }
        __syncthreads();
    }

    // combined S = (63*M1 + M2)/64
#pragma unroll
    for (int ni = 0; ni < 6; ++ni) {
        int row = wr * 16 + (lane >> 2);
        int col = wc * 48 + ni * 8 + (lane & 3) * 2;
        sS[row * S_STR + col]           = fmaf(63.f, a1[ni][0], a2[ni][0]) * INV_S;
        sS[row * S_STR + col + 1]       = fmaf(63.f, a1[ni][1], a2[ni][1]) * INV_S;
        sS[(row + 8) * S_STR + col]     = fmaf(63.f, a1[ni][2], a2[ni][2]) * INV_S;
        sS[(row + 8) * S_STR + col + 1] = fmaf(63.f, a1[ni][3], a2[ni][3]) * INV_S;
    }

    issueV(0, 0);
    issueV(1, 1);
    __syncthreads();

#pragma unroll
    for (int ii = 0; ii < 4; ++ii) {
        int i = wid * 4 + ii;
        float vals[4];
        float m = -CUDART_INF_F;
#pragma unroll
        for (int t = 0; t < 4; ++t) {
            vals[t] = sS[i * S_STR + i + lane + 32 * t];
            m = fmaxf(m, vals[t]);
        }
#pragma unroll
        for (int o = 16; o > 0; o >>= 1)
            m = fmaxf(m, __shfl_xor_sync(0xffffffffu, m, o));
        float s = 0.f;
#pragma unroll
        for (int t = 0; t < 4; ++t) s += __expf(vals[t] - m);
#pragma unroll
        for (int o = 16; o > 0; o >>= 1)
            s += __shfl_xor_sync(0xffffffffu, s, o);
        float inv = 1.f / s;
#pragma unroll
        for (int t = 0; t < 6; ++t) {
            int r = lane + 32 * t;
            int w = r - i;
            float val = (w >= 0 && w < WW) ? __expf(sS[i * S_STR + r] - m) * inv : 0.f;
            __half h = __float2half_rn(val);
            float hf = __half2float(h);
            __half pc = __float2half_rn(fmaf(SPLIT_S, val - hf, hf));
            sPh[i * P_STR + r] = h;
            sPc[i * P_STR + r] = pc;
        }
    }
    __syncthreads();

    float o1[16][4], o2[16][4];
#pragma unroll
    for (int ni = 0; ni < 16; ++ni)
#pragma unroll
        for (int q = 0; q < 4; ++q) { o1[ni][q] = 0.f; o2[ni][q] = 0.f; }

    const int pa_row = wr * 16 + (lane & 15);
    const int v_row  = (lane & 15);
    const int v_col0 = wc * 128 + ((lane >> 4) << 3);

    for (int c = 0; c < 6; ++c) {
        if (c < 5) asm volatile("cp.async.wait_group 1;" ::: "memory");
        else       asm volatile("cp.async.wait_group 0;" ::: "memory");
        __syncthreads();
        const int buf = c & 1;

#pragma unroll
        for (int ks = 0; ks < 2; ++ks) {
            int kg = c * 32 + ks * 16;
            uint32_t ph[4], pc[4];
            LDMX4(ph[0], ph[1], ph[2], ph[3],
                  sm + SM_PH + (uint32_t)(pa_row * P_STR + kg + (lane >> 4) * 8) * 2);
            LDMX4(pc[0], pc[1], pc[2], pc[3],
                  sm + SM_PC + (uint32_t)(pa_row * P_STR + kg + (lane >> 4) * 8) * 2);
#pragma unroll
            for (int nt = 0; nt < 8; ++nt) {
                uint32_t off = (uint32_t)((ks * 16 + v_row) * V_STR + v_col0 + nt * 16) * 2;
                uint32_t h0, h1, h2, h3, c0, c1, c2, c3;
                LDMX4T(h0, h1, h2, h3, sm + SM_VHb(buf) + off);
                LDMX4T(c0, c1, c2, c3, sm + SM_VCb(buf) + off);
                MMA16816(o1[2 * nt],     ph, h0, h1);
                MMA16816(o1[2 * nt + 1], ph, h2, h3);
                MMA16816(o2[2 * nt],     pc, c0, c1);
                MMA16816(o2[2 * nt + 1], pc, c2, c3);
            }
        }
        __syncthreads();
        if (c + 2 < 6) issueV(c + 2, buf);
    }

    const int orow = q0 + wr * 16 + (lane >> 2);
    const int ocol = wc * 128 + (lane & 3) * 2;
#pragma unroll
    for (int ni = 0; ni < 16; ++ni) {
        int col = ocol + ni * 8;
        *(float2*)&out[((size_t)(bbase + orow)) * DD + col] =
            make_float2(fmaf(63.f, o1[ni][0], o2[ni][0]) * INV_S,
                        fmaf(63.f, o1[ni][1], o2[ni][1]) * INV_S);
        *(float2*)&out[((size_t)(bbase + orow + 8)) * DD + col] =
            make_float2(fmaf(63.f, o1[ni][2], o2[ni][2]) * INV_S,
                        fmaf(63.f, o1[ni][3], o2[ni][3]) * INV_S);
    }
}

extern "C" void kernel_launch(void* const* d_in, const int* in_sizes, int n_in,
                              void* d_out, int out_size) {
    const float* x  = (const float*)d_in[0];
    const float* wl = (const float*)d_in[1];
    float* out = (float*)d_out;

    cudaFuncSetAttribute(qkv_mma_kernel,
                         cudaFuncAttributeMaxDynamicSharedMemorySize, SMEM_QKV);
    cudaFuncSetAttribute(attn_tc_kernel,
                         cudaFuncAttributeMaxDynamicSharedMemorySize, SMEM_ATTN);

    const int ntot = NX4 + NW4;
    conv_all_kernel<<<(ntot + 255) / 256, 256>>>(x, wl);

    dim3 g1(EE / 128, (BB * NN) / 128);   // 12 x 32
    qkv_mma_kernel<<<g1, 256, SMEM_QKV>>>();

    dim3 g2(NN / 32, BB);                 // 64 x 2
    attn_tc_kernel<<<g2, 256, SMEM_ATTN>>>(out);
}